// round 2
// baseline (speedup 1.0000x reference)
#include <cuda_runtime.h>
#include <cstdint>
#include <math.h>

#define HID   2048
#define DRES  1024
#define NRES  4
#define SRES  256
#define BB    4
#define TT    2048
#define MROWS (BB*TT)
#define LEAK  0.1f

// -------- scratch (static device globals; no allocation in kernel_launch) ----
__device__ float g_x[(size_t)MROWS * DRES];       // input projection  [8192,1024]
__device__ float g_states[(size_t)MROWS * DRES];  // reservoir states  [8192,1024]
__device__ float g_out[(size_t)MROWS * HID];      // output projection [8192,2048]
__device__ float g_final[BB * DRES];              // final state       [4,1024]

// ============================================================================
// tf32 mma.sync GEMM, 3-stage cp.async pipeline:
//   C[M,N] = A[M,K] @ B[K,N] + bias[N]
// 128x128 CTA tile, BK=32, 256 threads, warp tile 32x64 (m16n8k8)
// ============================================================================
__device__ __forceinline__ uint32_t f2tf32(float f) {
    uint32_t r; asm("cvt.rna.tf32.f32 %0, %1;" : "=r"(r) : "f"(f)); return r;
}

#define AS_STRIDE 36               // 32 + 4 pad (144B rows, 16B aligned)
#define BS_STRIDE 132              // 128 + 4 pad (528B rows, 16B aligned)
#define A_STAGE   (128 * AS_STRIDE)   // floats per A stage
#define B_STAGE   (32  * BS_STRIDE)   // floats per B stage
#define NSTAGE    3
#define GEMM_SMEM_BYTES ((NSTAGE * (A_STAGE + B_STAGE)) * 4)

#define CP_ASYNC_CG(dst, src) \
    asm volatile("cp.async.cg.shared.global [%0], [%1], 16;" :: "r"(dst), "l"(src))
#define CP_COMMIT() asm volatile("cp.async.commit_group;")
#define CP_WAIT1()  asm volatile("cp.async.wait_group 1;")

__global__ __launch_bounds__(256) void gemm_tf32_kernel(
    const float* __restrict__ A, const float* __restrict__ Bm,
    const float* __restrict__ bias, float* __restrict__ C,
    int M, int N, int K)
{
    extern __shared__ float smem[];
    float* As = smem;                         // [NSTAGE][128][AS_STRIDE]
    float* Bs = smem + NSTAGE * A_STAGE;      // [NSTAGE][32][BS_STRIDE]
    uint32_t smA = (uint32_t)__cvta_generic_to_shared(As);
    uint32_t smB = (uint32_t)__cvta_generic_to_shared(Bs);

    int tid = threadIdx.x;
    int wid = tid >> 5, lane = tid & 31;
    int g = lane >> 2, tig = lane & 3;
    int m0 = blockIdx.y * 128, n0 = blockIdx.x * 128;
    int wm = (wid >> 1) * 32;     // warp row base
    int wn = (wid & 1) * 64;      // warp col base

    // per-thread load coordinates (A: 4 float4, B: 4 float4 per stage)
    int arow[4], aquad[4], brow[4], bquad[4];
    #pragma unroll
    for (int i = 0; i < 4; i++) {
        int v = tid + i * 256;
        arow[i] = v >> 3;  aquad[i] = (v & 7)  << 2;
        brow[i] = v >> 5;  bquad[i] = (v & 31) << 2;
    }

    float acc[2][8][4];
    #pragma unroll
    for (int i = 0; i < 2; i++)
        #pragma unroll
        for (int j = 0; j < 8; j++)
            #pragma unroll
            for (int k = 0; k < 4; k++) acc[i][j][k] = 0.f;

    const int NK = K >> 5;   // number of BK=32 slices

    // ---- prologue: preload stage 0 and 1 ----
    #pragma unroll
    for (int s = 0; s < 2; s++) {
        int k0 = s * 32;
        #pragma unroll
        for (int i = 0; i < 4; i++) {
            const float* srcA = A + (size_t)(m0 + arow[i]) * K + k0 + aquad[i];
            CP_ASYNC_CG(smA + (uint32_t)((s * A_STAGE + arow[i] * AS_STRIDE + aquad[i]) * 4), srcA);
            const float* srcB = Bm + (size_t)(k0 + brow[i]) * N + n0 + bquad[i];
            CP_ASYNC_CG(smB + (uint32_t)((s * B_STAGE + brow[i] * BS_STRIDE + bquad[i]) * 4), srcB);
        }
        CP_COMMIT();
    }

    for (int it = 0; it < NK; it++) {
        CP_WAIT1();            // stage `it` landed (only newest 1 group may pend)
        __syncthreads();       // also fences: everyone done computing stage it-1

        // issue prefetch for stage it+2 (overwrites stage (it-1)%3: safe, synced)
        if (it + 2 < NK) {
            int s = (it + 2) % NSTAGE;
            int k0 = (it + 2) << 5;
            #pragma unroll
            for (int i = 0; i < 4; i++) {
                const float* srcA = A + (size_t)(m0 + arow[i]) * K + k0 + aquad[i];
                CP_ASYNC_CG(smA + (uint32_t)((s * A_STAGE + arow[i] * AS_STRIDE + aquad[i]) * 4), srcA);
                const float* srcB = Bm + (size_t)(k0 + brow[i]) * N + n0 + bquad[i];
                CP_ASYNC_CG(smB + (uint32_t)((s * B_STAGE + brow[i] * BS_STRIDE + bquad[i]) * 4), srcB);
            }
        }
        CP_COMMIT();           // one group per iteration keeps counting uniform

        // ---- compute on stage it%3 ----
        const float* as = As + (it % NSTAGE) * A_STAGE;
        const float* bs = Bs + (it % NSTAGE) * B_STAGE;
        #pragma unroll
        for (int ks = 0; ks < 32; ks += 8) {
            uint32_t af[2][4];
            #pragma unroll
            for (int tm = 0; tm < 2; tm++) {
                int rb = wm + tm * 16 + g;
                af[tm][0] = f2tf32(as[(rb     ) * AS_STRIDE + ks     + tig]);
                af[tm][1] = f2tf32(as[(rb +  8) * AS_STRIDE + ks     + tig]);
                af[tm][2] = f2tf32(as[(rb     ) * AS_STRIDE + ks + 4 + tig]);
                af[tm][3] = f2tf32(as[(rb +  8) * AS_STRIDE + ks + 4 + tig]);
            }
            uint32_t bf[8][2];
            #pragma unroll
            for (int tn = 0; tn < 8; tn++) {
                int col = wn + tn * 8 + g;
                bf[tn][0] = f2tf32(bs[(ks     + tig) * BS_STRIDE + col]);
                bf[tn][1] = f2tf32(bs[(ks + 4 + tig) * BS_STRIDE + col]);
            }
            #pragma unroll
            for (int tm = 0; tm < 2; tm++)
                #pragma unroll
                for (int tn = 0; tn < 8; tn++) {
                    asm volatile(
                        "mma.sync.aligned.m16n8k8.row.col.f32.tf32.tf32.f32 "
                        "{%0,%1,%2,%3}, {%4,%5,%6,%7}, {%8,%9}, {%0,%1,%2,%3};"
                        : "+f"(acc[tm][tn][0]), "+f"(acc[tm][tn][1]),
                          "+f"(acc[tm][tn][2]), "+f"(acc[tm][tn][3])
                        : "r"(af[tm][0]), "r"(af[tm][1]), "r"(af[tm][2]), "r"(af[tm][3]),
                          "r"(bf[tn][0]), "r"(bf[tn][1]));
                }
        }
    }

    // epilogue: add bias, store (float2 pairs are contiguous in N)
    #pragma unroll
    for (int tm = 0; tm < 2; tm++) {
        int row0 = m0 + wm + tm * 16 + g;
        #pragma unroll
        for (int tn = 0; tn < 8; tn++) {
            int col = n0 + wn + tn * 8 + tig * 2;
            float b0 = bias[col], b1 = bias[col + 1];
            float2 v0 = make_float2(acc[tm][tn][0] + b0, acc[tm][tn][1] + b1);
            float2 v1 = make_float2(acc[tm][tn][2] + b0, acc[tm][tn][3] + b1);
            *(float2*)(C + (size_t)row0 * N + col) = v0;
            *(float2*)(C + (size_t)(row0 + 8) * N + col) = v1;
        }
    }
}

// ============================================================================
// Reservoir scan: 16 chains (b,r), 4-CTA cluster per chain, W in registers.
// Each CTA owns 64 output rows; state exchanged via DSMEM + mbarriers.
// ============================================================================
__device__ __forceinline__ uint32_t su32(const void* p) {
    return (uint32_t)__cvta_generic_to_shared(p);
}

__device__ __forceinline__ void mbar_init(uint32_t a, uint32_t cnt) {
    asm volatile("mbarrier.init.shared.b64 [%0], %1;" :: "r"(a), "r"(cnt) : "memory");
}
__device__ __forceinline__ void mbar_arrive_local(uint32_t a) {
    asm volatile("mbarrier.arrive.shared.b64 _, [%0];" :: "r"(a) : "memory");
}
__device__ __forceinline__ void mbar_arrive_cluster(uint32_t local_addr, uint32_t rank) {
    asm volatile(
        "{\n\t.reg .b32 ra;\n\t"
        "mapa.shared::cluster.u32 ra, %0, %1;\n\t"
        "mbarrier.arrive.release.cluster.shared::cluster.b64 _, [ra];\n\t}"
        :: "r"(local_addr), "r"(rank) : "memory");
}
__device__ __forceinline__ void st_cluster_f32(uint32_t local_addr, uint32_t rank, float v) {
    asm volatile(
        "{\n\t.reg .b32 ra;\n\t"
        "mapa.shared::cluster.u32 ra, %0, %1;\n\t"
        "st.shared::cluster.f32 [ra], %2;\n\t}"
        :: "r"(local_addr), "r"(rank), "f"(v) : "memory");
}
__device__ __forceinline__ void mbar_wait_parity(uint32_t a, uint32_t parity) {
    uint32_t done;
    asm volatile(
        "{\n\t.reg .pred p;\n\t"
        "mbarrier.try_wait.parity.acquire.cluster.shared::cta.b64 p, [%1], %2, 0x989680;\n\t"
        "selp.b32 %0, 1, 0, p;\n\t}"
        : "=r"(done) : "r"(a), "r"(parity) : "memory");
    while (!done) {
        asm volatile(
            "{\n\t.reg .pred p;\n\t"
            "mbarrier.try_wait.parity.acquire.cluster.shared::cta.b64 p, [%1], %2, 0x989680;\n\t"
            "selp.b32 %0, 1, 0, p;\n\t}"
            : "=r"(done) : "r"(a), "r"(parity) : "memory");
    }
}

__global__ __launch_bounds__(256) __cluster_dims__(4, 1, 1)
void scan_kernel(const float* __restrict__ xin, const float* __restrict__ prev,
                 const float* __restrict__ wres, float* __restrict__ states,
                 float* __restrict__ finalst)
{
    // state buffers: 4 quarters of 64 floats, each padded to 68 (bank shift + 16B align)
    __shared__ float sbuf[2][4 * 68];
    __shared__ __align__(8) uint64_t mbar[2];

    int tid = threadIdx.x;
    uint32_t rank;
    asm("mov.u32 %0, %%cluster_ctarank;" : "=r"(rank));
    int chain = blockIdx.x >> 2;        // 0..15
    int b = chain >> 2, r = chain & 3;
    int klocal = tid >> 2;              // 0..63 : output row within this CTA
    int q = tid & 3;                    // j-quarter
    int kg = rank * 64 + klocal;        // global output row 0..255

    uint32_t sbuf_a[2] = { su32(&sbuf[0][0]), su32(&sbuf[1][0]) };
    uint32_t mbar_a[2] = { su32(&mbar[0]),    su32(&mbar[1])    };

    // ---- load my W chunk into registers: W[r][kg][q*64 .. q*64+63] ----
    float w[64];
    {
        const float* wp = wres + ((size_t)(r * 256 + kg) * 256 + q * 64);
        #pragma unroll
        for (int i = 0; i < 16; i++) {
            float4 v = *(const float4*)(wp + 4 * i);
            w[4*i] = v.x; w[4*i+1] = v.y; w[4*i+2] = v.z; w[4*i+3] = v.w;
        }
    }
    // ---- init state buffer 0 from prev_state (each CTA loads all 256) ----
    {
        int j = tid;
        sbuf[0][(j >> 6) * 68 + (j & 63)] = prev[b * 1024 + r * 256 + j];
    }
    if (tid == 0) {
        mbar_init(mbar_a[0], 4);
        mbar_init(mbar_a[1], 4);
    }
    __syncthreads();
    if (tid == 0) {   // pre-arm buffer 0 so step 0's wait passes
        mbar_arrive_local(mbar_a[0]); mbar_arrive_local(mbar_a[0]);
        mbar_arrive_local(mbar_a[0]); mbar_arrive_local(mbar_a[0]);
    }
    // all mbarriers must be visible cluster-wide before any remote arrive
    asm volatile("barrier.cluster.arrive.aligned;" ::: "memory");
    asm volatile("barrier.cluster.wait.aligned;"   ::: "memory");

    int mypos = (kg >> 6) * 68 + (kg & 63);
    const float* xbase = xin + (size_t)b * TT * 1024 + r * 256 + kg;
    float* stbase = states + (size_t)b * TT * 1024 + r * 256 + kg;

    for (int t = 0; t < TT; t++) {
        int cur = t & 1, nxt = cur ^ 1;
        float xv = 0.f;
        if (q == 0) xv = xbase[(size_t)t * 1024];   // overlap LDG with wait

        mbar_wait_parity(mbar_a[cur], (t >> 1) & 1);

        // partial dot: my quarter of row kg
        float acc = 0.f;
        const float* sp = &sbuf[cur][q * 68];
        #pragma unroll
        for (int i = 0; i < 16; i++) {
            float4 sv = *(const float4*)(sp + 4 * i);
            acc = fmaf(w[4*i  ], sv.x, acc);
            acc = fmaf(w[4*i+1], sv.y, acc);
            acc = fmaf(w[4*i+2], sv.z, acc);
            acc = fmaf(w[4*i+3], sv.w, acc);
        }
        acc += __shfl_xor_sync(0xffffffffu, acc, 1);
        acc += __shfl_xor_sync(0xffffffffu, acc, 2);

        if (q == 0) {
            float sold = sbuf[cur][mypos];
            float snew = (1.0f - LEAK) * sold + LEAK * tanhf(acc + xv);
            stbase[(size_t)t * 1024] = snew;
            if (t == TT - 1) finalst[b * 1024 + r * 256 + kg] = snew;
            uint32_t loc = sbuf_a[nxt] + (uint32_t)mypos * 4u;
            #pragma unroll
            for (uint32_t p = 0; p < 4; p++) st_cluster_f32(loc, p, snew);
        }
        __syncthreads();   // all reads of sbuf[cur] + all pushes done
        if (tid < 4) mbar_arrive_cluster(mbar_a[nxt], (uint32_t)tid);
    }

    // keep cluster alive until all in-flight DSMEM traffic lands
    asm volatile("barrier.cluster.arrive.aligned;" ::: "memory");
    asm volatile("barrier.cluster.wait.aligned;"   ::: "memory");
}

// ============================================================================
// RMSNorm epilogue: y = (hs + out) * rsqrt(mean((hs+out)^2) + eps) * ln_w
// ============================================================================
__global__ __launch_bounds__(256) void rmsnorm_kernel(
    const float* __restrict__ hs, const float* __restrict__ ot,
    const float* __restrict__ lnw, float* __restrict__ y)
{
    __shared__ float red[8];
    int row = blockIdx.x, tid = threadIdx.x;
    const float4* h4 = (const float4*)(hs + (size_t)row * HID);
    const float4* o4 = (const float4*)(ot + (size_t)row * HID);
    const float4* l4 = (const float4*)lnw;
    float4* y4 = (float4*)(y + (size_t)row * HID);

    float4 v[2];
    float ss = 0.f;
    #pragma unroll
    for (int i = 0; i < 2; i++) {
        int idx = tid + i * 256;
        float4 a = h4[idx], b = o4[idx];
        float4 s = make_float4(a.x + b.x, a.y + b.y, a.z + b.z, a.w + b.w);
        v[i] = s;
        ss += s.x * s.x + s.y * s.y + s.z * s.z + s.w * s.w;
    }
    #pragma unroll
    for (int off = 16; off; off >>= 1) ss += __shfl_xor_sync(0xffffffffu, ss, off);
    if ((tid & 31) == 0) red[tid >> 5] = ss;
    __syncthreads();
    float tot = 0.f;
    #pragma unroll
    for (int i = 0; i < 8; i++) tot += red[i];
    float scale = rsqrtf(tot * (1.0f / HID) + 1e-6f);
    #pragma unroll
    for (int i = 0; i < 2; i++) {
        int idx = tid + i * 256;
        float4 lw = l4[idx];
        float4 s = v[i];
        y4[idx] = make_float4(s.x * scale * lw.x, s.y * scale * lw.y,
                              s.z * scale * lw.z, s.w * scale * lw.w);
    }
}

__global__ void copy_final_kernel(float* __restrict__ dst) {
    int i = blockIdx.x * 256 + threadIdx.x;
    if (i < BB * DRES) dst[i] = g_final[i];
}

// ============================================================================
extern "C" void kernel_launch(void* const* d_in, const int* in_sizes, int n_in,
                              void* d_out, int out_size)
{
    const float* hs   = (const float*)d_in[0];
    const float* prev = (const float*)d_in[1];
    const float* w_in = (const float*)d_in[2];
    const float* b_in = (const float*)d_in[3];
    const float* wres = (const float*)d_in[4];
    const float* wout = (const float*)d_in[5];
    const float* bout = (const float*)d_in[6];
    const float* lnw  = (const float*)d_in[7];
    float* out = (float*)d_out;

    void *px, *ps, *po, *pf;
    cudaGetSymbolAddress(&px, g_x);
    cudaGetSymbolAddress(&ps, g_states);
    cudaGetSymbolAddress(&po, g_out);
    cudaGetSymbolAddress(&pf, g_final);
    float* gx = (float*)px;
    float* gs = (float*)ps;
    float* go = (float*)po;
    float* gf = (float*)pf;

    static bool attr_set = false;
    if (!attr_set) {
        cudaFuncSetAttribute(gemm_tf32_kernel,
                             cudaFuncAttributeMaxDynamicSharedMemorySize,
                             GEMM_SMEM_BYTES);
        attr_set = true;
    }

    // 1) x = hs @ w_in + b_in        [8192,1024]
    gemm_tf32_kernel<<<dim3(DRES / 128, MROWS / 128), 256, GEMM_SMEM_BYTES>>>(
        hs, w_in, b_in, gx, MROWS, DRES, HID);

    // 2) reservoir scan -> states, final
    scan_kernel<<<64, 256>>>(gx, prev, wres, gs, gf);

    // 3) out = states @ w_out + b_out  [8192,2048]
    gemm_tf32_kernel<<<dim3(HID / 128, MROWS / 128), 256, GEMM_SMEM_BYTES>>>(
        gs, wout, bout, go, MROWS, HID, DRES);

    // 4) y = RMSNorm(hs + out) * ln_w
    rmsnorm_kernel<<<MROWS, 256>>>(hs, go, lnw, out);

    // 5) final state appended after y (if the output buffer carries it)
    if (out_size >= MROWS * HID + BB * DRES) {
        float* fdst = out + (out_size - BB * DRES);
        copy_final_kernel<<<(BB * DRES + 255) / 256, 256>>>(fdst);
    }
}

// round 3
// speedup vs baseline: 1.2620x; 1.2620x over previous
#include <cuda_runtime.h>
#include <cstdint>
#include <math.h>

#define HID   2048
#define DRES  1024
#define NRES  4
#define SRES  256
#define BB    4
#define TT    2048
#define MROWS (BB*TT)
#define LEAK  0.1f
#define SPCAP 64          // sparse row capacity (true max nnz ~44 @ p=0.1)

// -------- scratch (static device globals; no allocation in kernel_launch) ----
__device__ float g_x[(size_t)MROWS * DRES];       // input projection  [8192,1024]
__device__ float g_states[(size_t)MROWS * DRES];  // reservoir states  [8192,1024]
__device__ float g_out[(size_t)MROWS * HID];      // output projection [8192,2048]
__device__ float g_final[BB * DRES];              // final state       [4,1024]
__device__ float    g_spv[NRES][SPCAP][SRES];     // sparse values  [r][slot][row]
__device__ uint32_t g_spo[NRES][SPCAP][SRES];     // byte offsets   [r][slot][row]

// ============================================================================
// tf32 mma.sync GEMM, 3-stage cp.async pipeline:
//   C[M,N] = A[M,K] @ B[K,N] + bias[N]
// 128x128 CTA tile, BK=32, 256 threads, warp tile 32x64 (m16n8k8)
// ============================================================================
__device__ __forceinline__ uint32_t f2tf32(float f) {
    uint32_t r; asm("cvt.rna.tf32.f32 %0, %1;" : "=r"(r) : "f"(f)); return r;
}

#define AS_STRIDE 36
#define BS_STRIDE 132
#define A_STAGE   (128 * AS_STRIDE)
#define B_STAGE   (32  * BS_STRIDE)
#define NSTAGE    3
#define GEMM_SMEM_BYTES ((NSTAGE * (A_STAGE + B_STAGE)) * 4)

#define CP_ASYNC_CG(dst, src) \
    asm volatile("cp.async.cg.shared.global [%0], [%1], 16;" :: "r"(dst), "l"(src))
#define CP_COMMIT() asm volatile("cp.async.commit_group;")
#define CP_WAIT1()  asm volatile("cp.async.wait_group 1;")

__global__ __launch_bounds__(256) void gemm_tf32_kernel(
    const float* __restrict__ A, const float* __restrict__ Bm,
    const float* __restrict__ bias, float* __restrict__ C,
    int M, int N, int K)
{
    extern __shared__ float smem[];
    float* As = smem;
    float* Bs = smem + NSTAGE * A_STAGE;
    uint32_t smA = (uint32_t)__cvta_generic_to_shared(As);
    uint32_t smB = (uint32_t)__cvta_generic_to_shared(Bs);

    int tid = threadIdx.x;
    int wid = tid >> 5, lane = tid & 31;
    int g = lane >> 2, tig = lane & 3;
    int m0 = blockIdx.y * 128, n0 = blockIdx.x * 128;
    int wm = (wid >> 1) * 32;
    int wn = (wid & 1) * 64;

    int arow[4], aquad[4], brow[4], bquad[4];
    #pragma unroll
    for (int i = 0; i < 4; i++) {
        int v = tid + i * 256;
        arow[i] = v >> 3;  aquad[i] = (v & 7)  << 2;
        brow[i] = v >> 5;  bquad[i] = (v & 31) << 2;
    }

    float acc[2][8][4];
    #pragma unroll
    for (int i = 0; i < 2; i++)
        #pragma unroll
        for (int j = 0; j < 8; j++)
            #pragma unroll
            for (int k = 0; k < 4; k++) acc[i][j][k] = 0.f;

    const int NK = K >> 5;

    #pragma unroll
    for (int s = 0; s < 2; s++) {
        int k0 = s * 32;
        #pragma unroll
        for (int i = 0; i < 4; i++) {
            const float* srcA = A + (size_t)(m0 + arow[i]) * K + k0 + aquad[i];
            CP_ASYNC_CG(smA + (uint32_t)((s * A_STAGE + arow[i] * AS_STRIDE + aquad[i]) * 4), srcA);
            const float* srcB = Bm + (size_t)(k0 + brow[i]) * N + n0 + bquad[i];
            CP_ASYNC_CG(smB + (uint32_t)((s * B_STAGE + brow[i] * BS_STRIDE + bquad[i]) * 4), srcB);
        }
        CP_COMMIT();
    }

    for (int it = 0; it < NK; it++) {
        CP_WAIT1();
        __syncthreads();

        if (it + 2 < NK) {
            int s = (it + 2) % NSTAGE;
            int k0 = (it + 2) << 5;
            #pragma unroll
            for (int i = 0; i < 4; i++) {
                const float* srcA = A + (size_t)(m0 + arow[i]) * K + k0 + aquad[i];
                CP_ASYNC_CG(smA + (uint32_t)((s * A_STAGE + arow[i] * AS_STRIDE + aquad[i]) * 4), srcA);
                const float* srcB = Bm + (size_t)(k0 + brow[i]) * N + n0 + bquad[i];
                CP_ASYNC_CG(smB + (uint32_t)((s * B_STAGE + brow[i] * BS_STRIDE + bquad[i]) * 4), srcB);
            }
        }
        CP_COMMIT();

        const float* as = As + (it % NSTAGE) * A_STAGE;
        const float* bs = Bs + (it % NSTAGE) * B_STAGE;
        #pragma unroll
        for (int ks = 0; ks < 32; ks += 8) {
            uint32_t af[2][4];
            #pragma unroll
            for (int tm = 0; tm < 2; tm++) {
                int rb = wm + tm * 16 + g;
                af[tm][0] = f2tf32(as[(rb     ) * AS_STRIDE + ks     + tig]);
                af[tm][1] = f2tf32(as[(rb +  8) * AS_STRIDE + ks     + tig]);
                af[tm][2] = f2tf32(as[(rb     ) * AS_STRIDE + ks + 4 + tig]);
                af[tm][3] = f2tf32(as[(rb +  8) * AS_STRIDE + ks + 4 + tig]);
            }
            uint32_t bf[8][2];
            #pragma unroll
            for (int tn = 0; tn < 8; tn++) {
                int col = wn + tn * 8 + g;
                bf[tn][0] = f2tf32(bs[(ks     + tig) * BS_STRIDE + col]);
                bf[tn][1] = f2tf32(bs[(ks + 4 + tig) * BS_STRIDE + col]);
            }
            #pragma unroll
            for (int tm = 0; tm < 2; tm++)
                #pragma unroll
                for (int tn = 0; tn < 8; tn++) {
                    asm volatile(
                        "mma.sync.aligned.m16n8k8.row.col.f32.tf32.tf32.f32 "
                        "{%0,%1,%2,%3}, {%4,%5,%6,%7}, {%8,%9}, {%0,%1,%2,%3};"
                        : "+f"(acc[tm][tn][0]), "+f"(acc[tm][tn][1]),
                          "+f"(acc[tm][tn][2]), "+f"(acc[tm][tn][3])
                        : "r"(af[tm][0]), "r"(af[tm][1]), "r"(af[tm][2]), "r"(af[tm][3]),
                          "r"(bf[tn][0]), "r"(bf[tn][1]));
                }
        }
    }

    #pragma unroll
    for (int tm = 0; tm < 2; tm++) {
        int row0 = m0 + wm + tm * 16 + g;
        #pragma unroll
        for (int tn = 0; tn < 8; tn++) {
            int col = n0 + wn + tn * 8 + tig * 2;
            float b0 = bias[col], b1 = bias[col + 1];
            float2 v0 = make_float2(acc[tm][tn][0] + b0, acc[tm][tn][1] + b1);
            float2 v1 = make_float2(acc[tm][tn][2] + b0, acc[tm][tn][3] + b1);
            *(float2*)(C + (size_t)row0 * N + col) = v0;
            *(float2*)(C + (size_t)(row0 + 8) * N + col) = v1;
        }
    }
}

// ============================================================================
// Sparse compression of w_res: per row, pack nonzeros into SPCAP slots.
// Slot-major layout so the scan kernel's loads are coalesced across rows.
// Deterministic, runs every launch.
// ============================================================================
__global__ void build_sparse_kernel(const float* __restrict__ wres)
{
    int r = blockIdx.x;       // 0..3
    int k = threadIdx.x;      // 0..255 : row
    const float* row = wres + ((size_t)(r * SRES + k)) * SRES;
    int cnt = 0;
    for (int j = 0; j < SRES; j++) {
        float w = row[j];
        if (w != 0.0f && cnt < SPCAP) {
            g_spv[r][cnt][k] = w;
            g_spo[r][cnt][k] = (uint32_t)(j * 4);   // byte offset into s[]
            cnt++;
        }
    }
    for (; cnt < SPCAP; cnt++) {
        g_spv[r][cnt][k] = 0.0f;   // padded FMA: += 0 * s[0]
        g_spo[r][cnt][k] = 0u;
    }
}

// ============================================================================
// Sparse reservoir scan: 1 CTA per chain (b,r), 256 threads, thread = row.
// Sparse row (values + pre-biased smem addresses) lives in registers.
// State lives in smem; no clusters / mbarriers / DSMEM.
// ============================================================================
__global__ __launch_bounds__(256) void scan_sparse_kernel(
    const float* __restrict__ xin, const float* __restrict__ prev,
    float* __restrict__ states, float* __restrict__ finalst)
{
    __shared__ float s[SRES];

    int chain = blockIdx.x;          // 0..15
    int b = chain >> 2, r = chain & 3;
    int k = threadIdx.x;             // row 0..255
    uint32_t sbase = (uint32_t)__cvta_generic_to_shared(s);

    // load sparse row into registers (coalesced: slot-major)
    float    val[SPCAP];
    uint32_t adr[SPCAP];
    #pragma unroll
    for (int i = 0; i < SPCAP; i++) {
        val[i] = g_spv[r][i][k];
        adr[i] = g_spo[r][i][k] + sbase;
    }

    float sreg = prev[b * DRES + r * SRES + k];
    s[k] = sreg;

    const float* xp = xin    + (size_t)b * TT * DRES + r * SRES + k;
    float*       sp = states + (size_t)b * TT * DRES + r * SRES + k;
    float xv = xp[0];
    __syncthreads();

    for (int t = 0; t < TT; t++) {
        // prefetch next timestep's x while we compute
        float xn = 0.f;
        if (t + 1 < TT) xn = xp[(size_t)(t + 1) * DRES];

        float a0 = 0.f, a1 = 0.f, a2 = 0.f, a3 = 0.f;
        #pragma unroll
        for (int i = 0; i < SPCAP; i += 4) {
            float s0, s1, s2, s3;
            asm volatile("ld.shared.f32 %0, [%1];" : "=f"(s0) : "r"(adr[i    ]));
            asm volatile("ld.shared.f32 %0, [%1];" : "=f"(s1) : "r"(adr[i + 1]));
            asm volatile("ld.shared.f32 %0, [%1];" : "=f"(s2) : "r"(adr[i + 2]));
            asm volatile("ld.shared.f32 %0, [%1];" : "=f"(s3) : "r"(adr[i + 3]));
            a0 = fmaf(val[i    ], s0, a0);
            a1 = fmaf(val[i + 1], s1, a1);
            a2 = fmaf(val[i + 2], s2, a2);
            a3 = fmaf(val[i + 3], s3, a3);
        }
        float pre = (a0 + a1) + (a2 + a3) + xv;
        float snew = (1.0f - LEAK) * sreg + LEAK * tanhf(pre);

        sp[(size_t)t * DRES] = snew;       // coalesced STG

        __syncthreads();                   // all gathers of s (step t) done
        s[k] = snew;
        sreg = snew;
        xv = xn;
        __syncthreads();                   // new state visible
    }

    finalst[b * DRES + r * SRES + k] = sreg;
}

// ============================================================================
// RMSNorm epilogue: y = (hs + out) * rsqrt(mean((hs+out)^2) + eps) * ln_w
// ============================================================================
__global__ __launch_bounds__(256) void rmsnorm_kernel(
    const float* __restrict__ hs, const float* __restrict__ ot,
    const float* __restrict__ lnw, float* __restrict__ y)
{
    __shared__ float red[8];
    int row = blockIdx.x, tid = threadIdx.x;
    const float4* h4 = (const float4*)(hs + (size_t)row * HID);
    const float4* o4 = (const float4*)(ot + (size_t)row * HID);
    const float4* l4 = (const float4*)lnw;
    float4* y4 = (float4*)(y + (size_t)row * HID);

    float4 v[2];
    float ss = 0.f;
    #pragma unroll
    for (int i = 0; i < 2; i++) {
        int idx = tid + i * 256;
        float4 a = h4[idx], b = o4[idx];
        float4 s = make_float4(a.x + b.x, a.y + b.y, a.z + b.z, a.w + b.w);
        v[i] = s;
        ss += s.x * s.x + s.y * s.y + s.z * s.z + s.w * s.w;
    }
    #pragma unroll
    for (int off = 16; off; off >>= 1) ss += __shfl_xor_sync(0xffffffffu, ss, off);
    if ((tid & 31) == 0) red[tid >> 5] = ss;
    __syncthreads();
    float tot = 0.f;
    #pragma unroll
    for (int i = 0; i < 8; i++) tot += red[i];
    float scale = rsqrtf(tot * (1.0f / HID) + 1e-6f);
    #pragma unroll
    for (int i = 0; i < 2; i++) {
        int idx = tid + i * 256;
        float4 lw = l4[idx];
        float4 s = v[i];
        y4[idx] = make_float4(s.x * scale * lw.x, s.y * scale * lw.y,
                              s.z * scale * lw.z, s.w * scale * lw.w);
    }
}

__global__ void copy_final_kernel(float* __restrict__ dst) {
    int i = blockIdx.x * 256 + threadIdx.x;
    if (i < BB * DRES) dst[i] = g_final[i];
}

// ============================================================================
extern "C" void kernel_launch(void* const* d_in, const int* in_sizes, int n_in,
                              void* d_out, int out_size)
{
    const float* hs   = (const float*)d_in[0];
    const float* prev = (const float*)d_in[1];
    const float* w_in = (const float*)d_in[2];
    const float* b_in = (const float*)d_in[3];
    const float* wres = (const float*)d_in[4];
    const float* wout = (const float*)d_in[5];
    const float* bout = (const float*)d_in[6];
    const float* lnw  = (const float*)d_in[7];
    float* out = (float*)d_out;

    void *px, *ps, *po, *pf;
    cudaGetSymbolAddress(&px, g_x);
    cudaGetSymbolAddress(&ps, g_states);
    cudaGetSymbolAddress(&po, g_out);
    cudaGetSymbolAddress(&pf, g_final);
    float* gx = (float*)px;
    float* gs = (float*)ps;
    float* go = (float*)po;
    float* gf = (float*)pf;

    static bool attr_set = false;
    if (!attr_set) {
        cudaFuncSetAttribute(gemm_tf32_kernel,
                             cudaFuncAttributeMaxDynamicSharedMemorySize,
                             GEMM_SMEM_BYTES);
        attr_set = true;
    }

    // 0) compress w_res rows (overlaps nothing; tiny)
    build_sparse_kernel<<<NRES, SRES>>>(wres);

    // 1) x = hs @ w_in + b_in        [8192,1024]
    gemm_tf32_kernel<<<dim3(DRES / 128, MROWS / 128), 256, GEMM_SMEM_BYTES>>>(
        hs, w_in, b_in, gx, MROWS, DRES, HID);

    // 2) sparse reservoir scan -> states, final
    scan_sparse_kernel<<<16, 256>>>(gx, prev, gs, gf);

    // 3) out = states @ w_out + b_out  [8192,2048]
    gemm_tf32_kernel<<<dim3(HID / 128, MROWS / 128), 256, GEMM_SMEM_BYTES>>>(
        gs, wout, bout, go, MROWS, HID, DRES);

    // 4) y = RMSNorm(hs + out) * ln_w
    rmsnorm_kernel<<<MROWS, 256>>>(hs, go, lnw, out);

    // 5) final state appended after y (if the output buffer carries it)
    if (out_size >= MROWS * HID + BB * DRES) {
        float* fdst = out + (out_size - BB * DRES);
        copy_final_kernel<<<(BB * DRES + 255) / 256, 256>>>(fdst);
    }
}

// round 6
// speedup vs baseline: 1.6334x; 1.2943x over previous
#include <cuda_runtime.h>
#include <cstdint>
#include <math.h>

#define HID   2048
#define DRES  1024
#define NRES  4
#define SRES  256
#define BB    4
#define TT    2048
#define MROWS (BB*TT)
#define LEAK  0.1f
#define SPCAP 64          // slot-position capacity (true max nnz ~44 @ p=0.1)

// -------- scratch (static device globals; no allocation in kernel_launch) ----
__device__ float g_x[(size_t)MROWS * DRES];       // input projection  [8192,1024]
__device__ float g_states[(size_t)MROWS * DRES];  // reservoir states  [8192,1024]
__device__ float g_out[(size_t)MROWS * HID];      // output projection [8192,2048]
__device__ float g_final[BB * DRES];              // final state       [4,1024]
__device__ float    g_spv[NRES][SPCAP][SRES];     // sparse values  [r][slot][row]
__device__ uint32_t g_spo[NRES][SPCAP][SRES];     // byte offsets   [r][slot][row]
__device__ int      g_spn[NRES][8];               // padded slot count per warp

// ============================================================================
// tf32 mma.sync GEMM, 3-stage cp.async pipeline (validated: 284us @ M=8192,N=2048,K=1024)
// ============================================================================
__device__ __forceinline__ uint32_t f2tf32(float f) {
    uint32_t r; asm("cvt.rna.tf32.f32 %0, %1;" : "=r"(r) : "f"(f)); return r;
}

#define AS_STRIDE 36
#define BS_STRIDE 132
#define A_STAGE   (128 * AS_STRIDE)
#define B_STAGE   (32  * BS_STRIDE)
#define NSTAGE    3
#define GEMM_SMEM_BYTES ((NSTAGE * (A_STAGE + B_STAGE)) * 4)

#define CP_ASYNC_CG(dst, src) \
    asm volatile("cp.async.cg.shared.global [%0], [%1], 16;" :: "r"(dst), "l"(src))
#define CP_COMMIT() asm volatile("cp.async.commit_group;")
#define CP_WAIT1()  asm volatile("cp.async.wait_group 1;")

__global__ __launch_bounds__(256) void gemm_tf32_kernel(
    const float* __restrict__ A, const float* __restrict__ Bm,
    const float* __restrict__ bias, float* __restrict__ C,
    int M, int N, int K)
{
    extern __shared__ float smem[];
    float* As = smem;
    float* Bs = smem + NSTAGE * A_STAGE;
    uint32_t smA = (uint32_t)__cvta_generic_to_shared(As);
    uint32_t smB = (uint32_t)__cvta_generic_to_shared(Bs);

    int tid = threadIdx.x;
    int wid = tid >> 5, lane = tid & 31;
    int g = lane >> 2, tig = lane & 3;
    int m0 = blockIdx.y * 128, n0 = blockIdx.x * 128;
    int wm = (wid >> 1) * 32;
    int wn = (wid & 1) * 64;

    int arow[4], aquad[4], brow[4], bquad[4];
    #pragma unroll
    for (int i = 0; i < 4; i++) {
        int v = tid + i * 256;
        arow[i] = v >> 3;  aquad[i] = (v & 7)  << 2;
        brow[i] = v >> 5;  bquad[i] = (v & 31) << 2;
    }

    float acc[2][8][4];
    #pragma unroll
    for (int i = 0; i < 2; i++)
        #pragma unroll
        for (int j = 0; j < 8; j++)
            #pragma unroll
            for (int k = 0; k < 4; k++) acc[i][j][k] = 0.f;

    const int NK = K >> 5;

    #pragma unroll
    for (int s = 0; s < 2; s++) {
        int k0 = s * 32;
        #pragma unroll
        for (int i = 0; i < 4; i++) {
            const float* srcA = A + (size_t)(m0 + arow[i]) * K + k0 + aquad[i];
            CP_ASYNC_CG(smA + (uint32_t)((s * A_STAGE + arow[i] * AS_STRIDE + aquad[i]) * 4), srcA);
            const float* srcB = Bm + (size_t)(k0 + brow[i]) * N + n0 + bquad[i];
            CP_ASYNC_CG(smB + (uint32_t)((s * B_STAGE + brow[i] * BS_STRIDE + bquad[i]) * 4), srcB);
        }
        CP_COMMIT();
    }

    for (int it = 0; it < NK; it++) {
        CP_WAIT1();
        __syncthreads();

        if (it + 2 < NK) {
            int s = (it + 2) % NSTAGE;
            int k0 = (it + 2) << 5;
            #pragma unroll
            for (int i = 0; i < 4; i++) {
                const float* srcA = A + (size_t)(m0 + arow[i]) * K + k0 + aquad[i];
                CP_ASYNC_CG(smA + (uint32_t)((s * A_STAGE + arow[i] * AS_STRIDE + aquad[i]) * 4), srcA);
                const float* srcB = Bm + (size_t)(k0 + brow[i]) * N + n0 + bquad[i];
                CP_ASYNC_CG(smB + (uint32_t)((s * B_STAGE + brow[i] * BS_STRIDE + bquad[i]) * 4), srcB);
            }
        }
        CP_COMMIT();

        const float* as = As + (it % NSTAGE) * A_STAGE;
        const float* bs = Bs + (it % NSTAGE) * B_STAGE;
        #pragma unroll
        for (int ks = 0; ks < 32; ks += 8) {
            uint32_t af[2][4];
            #pragma unroll
            for (int tm = 0; tm < 2; tm++) {
                int rb = wm + tm * 16 + g;
                af[tm][0] = f2tf32(as[(rb     ) * AS_STRIDE + ks     + tig]);
                af[tm][1] = f2tf32(as[(rb +  8) * AS_STRIDE + ks     + tig]);
                af[tm][2] = f2tf32(as[(rb     ) * AS_STRIDE + ks + 4 + tig]);
                af[tm][3] = f2tf32(as[(rb +  8) * AS_STRIDE + ks + 4 + tig]);
            }
            uint32_t bf[8][2];
            #pragma unroll
            for (int tn = 0; tn < 8; tn++) {
                int col = wn + tn * 8 + g;
                bf[tn][0] = f2tf32(bs[(ks     + tig) * BS_STRIDE + col]);
                bf[tn][1] = f2tf32(bs[(ks + 4 + tig) * BS_STRIDE + col]);
            }
            #pragma unroll
            for (int tm = 0; tm < 2; tm++)
                #pragma unroll
                for (int tn = 0; tn < 8; tn++) {
                    asm volatile(
                        "mma.sync.aligned.m16n8k8.row.col.f32.tf32.tf32.f32 "
                        "{%0,%1,%2,%3}, {%4,%5,%6,%7}, {%8,%9}, {%0,%1,%2,%3};"
                        : "+f"(acc[tm][tn][0]), "+f"(acc[tm][tn][1]),
                          "+f"(acc[tm][tn][2]), "+f"(acc[tm][tn][3])
                        : "r"(af[tm][0]), "r"(af[tm][1]), "r"(af[tm][2]), "r"(af[tm][3]),
                          "r"(bf[tn][0]), "r"(bf[tn][1]));
                }
        }
    }

    #pragma unroll
    for (int tm = 0; tm < 2; tm++) {
        int row0 = m0 + wm + tm * 16 + g;
        #pragma unroll
        for (int tn = 0; tn < 8; tn++) {
            int col = n0 + wn + tn * 8 + tig * 2;
            float b0 = bias[col], b1 = bias[col + 1];
            float2 v0 = make_float2(acc[tm][tn][0] + b0, acc[tm][tn][1] + b1);
            float2 v1 = make_float2(acc[tm][tn][2] + b0, acc[tm][tn][3] + b1);
            *(float2*)(C + (size_t)row0 * N + col) = v0;
            *(float2*)(C + (size_t)(row0 + 8) * N + col) = v1;
        }
    }
}

// ============================================================================
// Bank-scheduled sparse compression of w_res.
// Per warp (32 rows): greedily place each nonzero (row, j) into a slot
// position p so that each position touches each smem bank at most once.
// Padding lanes at a position share one identical free-bank address
// (broadcast = conflict-free). One block per reservoir r.
// Every g_spv/g_spo element is written every launch (deterministic).
// ============================================================================
__global__ __launch_bounds__(256) void build_sparse_kernel(const float* __restrict__ wres)
{
    __shared__ unsigned long long bankused[8][32];  // [warp][bank] -> position mask
    __shared__ unsigned long long rmask[256];       // per-row placed-position mask
    __shared__ int maxpos_s[8];
    __shared__ uint32_t padw_s[8][SPCAP];           // pad bank per (warp, position)

    int r = blockIdx.x;
    int k = threadIdx.x;            // row
    int w = k >> 5, lane = k & 31;

    if (lane == 0) maxpos_s[w] = -1;
    bankused[w][lane] = 0ull;
    rmask[k] = 0ull;

    // phase 1: compact my row's nonzeros
    int jlist[SPCAP]; float vlist[SPCAP];
    int cnt = 0;
    const float* rowp = wres + ((size_t)(r * SRES + k)) * SRES;
    for (int j = 0; j < SRES; j++) {
        float wv = rowp[j];
        if (wv != 0.0f && cnt < SPCAP) { jlist[cnt] = j; vlist[cnt] = wv; cnt++; }
    }
    __syncthreads();

    // phase 2: serialized placement within each warp (lanes take turns)
    for (int l = 0; l < 32; l++) {
        if (lane == l) {
            unsigned long long rm = 0ull;
            int mp = maxpos_s[w];
            for (int i = 0; i < cnt; i++) {
                int bank = jlist[i] & 31;
                unsigned long long blocked = bankused[w][bank] | rm;
                unsigned long long freeM = ~blocked;
                int pos;
                if (freeM != 0ull) pos = __ffsll((long long)freeM) - 1;
                else {
                    unsigned long long f2 = ~rm;
                    if (f2 == 0ull) continue;             // row full (impossible)
                    pos = __ffsll((long long)f2) - 1;
                }
                if (pos < 0 || pos >= SPCAP) continue;
                bankused[w][bank] |= 1ull << pos;
                rm |= 1ull << pos;
                g_spv[r][pos][k] = vlist[i];
                g_spo[r][pos][k] = (uint32_t)(jlist[i] * 4);
                if (pos > mp) mp = pos;
            }
            rmask[k] = rm;
            maxpos_s[w] = mp;
        }
        __syncwarp();
    }
    __syncthreads();

    int np = ((maxpos_s[w] + 1) + 3) & ~3;
    if (np < 4) np = 4;
    if (np > SPCAP) np = SPCAP;

    // phase 3a: pick a pad bank (free bank) for each (warp, position)
    for (int p = lane; p < SPCAP; p += 32) {
        uint32_t usedbanks = 0;
        #pragma unroll
        for (int bk = 0; bk < 32; bk++)
            usedbanks |= (uint32_t)((bankused[w][bk] >> p) & 1ull) << bk;
        uint32_t freeb = ~usedbanks;
        padw_s[w][p] = freeb ? (uint32_t)(__ffs(freeb) - 1) : 0u;
    }
    __syncthreads();

    // phase 3b: fill pads for every position this row didn't use (full SPCAP:
    // positions >= np are never read, but writing them keeps state deterministic)
    unsigned long long rm = rmask[k];
    for (int p = 0; p < SPCAP; p++) {
        if (!((rm >> p) & 1ull)) {
            g_spv[r][p][k] = 0.0f;
            g_spo[r][p][k] = padw_s[w][p] * 4u;
        }
    }
    if (lane == 0) g_spn[r][w] = np;
}

// ============================================================================
// Sparse reservoir scan: 1 CTA per chain (b,r), 256 threads, thread = row.
// Bank-scheduled slots -> conflict-free gathers; uniform per-warp trip count.
// ============================================================================
__device__ __forceinline__ float fast_tanh(float x) {
    // tanh(x) = 1 - 2/(exp(2x)+1); __expf rel-err ~1e-7, fine vs 1e-3 budget
    return 1.0f - 2.0f / (__expf(2.0f * x) + 1.0f);
}

__global__ __launch_bounds__(256) void scan_sparse_kernel(
    const float* __restrict__ xin, const float* __restrict__ prev,
    float* __restrict__ states, float* __restrict__ finalst)
{
    __shared__ float s[SRES];

    int chain = blockIdx.x;          // 0..15
    int b = chain >> 2, r = chain & 3;
    int k = threadIdx.x;             // row 0..255
    uint32_t sbase = (uint32_t)__cvta_generic_to_shared(s);

    const int nslots = g_spn[r][k >> 5];   // uniform within warp

    float    val[SPCAP];
    uint32_t adr[SPCAP];
    #pragma unroll
    for (int i = 0; i < SPCAP; i++) {
        val[i] = g_spv[r][i][k];
        adr[i] = g_spo[r][i][k] + sbase;
    }

    float sreg = prev[b * DRES + r * SRES + k];
    s[k] = sreg;

    const float* xp = xin    + (size_t)b * TT * DRES + r * SRES + k;
    float*       sp = states + (size_t)b * TT * DRES + r * SRES + k;
    float xv = xp[0];
    __syncthreads();

    for (int t = 0; t < TT; t++) {
        float xn = 0.f;
        if (t + 1 < TT) xn = xp[(size_t)(t + 1) * DRES];

        float a0 = 0.f, a1 = 0.f, a2 = 0.f, a3 = 0.f;
        #pragma unroll
        for (int i = 0; i < SPCAP; i += 4) {
            if (i >= nslots) break;          // uniform per warp
            float s0, s1, s2, s3;
            asm volatile("ld.shared.f32 %0, [%1];" : "=f"(s0) : "r"(adr[i    ]));
            asm volatile("ld.shared.f32 %0, [%1];" : "=f"(s1) : "r"(adr[i + 1]));
            asm volatile("ld.shared.f32 %0, [%1];" : "=f"(s2) : "r"(adr[i + 2]));
            asm volatile("ld.shared.f32 %0, [%1];" : "=f"(s3) : "r"(adr[i + 3]));
            a0 = fmaf(val[i    ], s0, a0);
            a1 = fmaf(val[i + 1], s1, a1);
            a2 = fmaf(val[i + 2], s2, a2);
            a3 = fmaf(val[i + 3], s3, a3);
        }
        float pre = (a0 + a1) + (a2 + a3) + xv;
        float snew = (1.0f - LEAK) * sreg + LEAK * fast_tanh(pre);

        sp[(size_t)t * DRES] = snew;       // coalesced STG

        __syncthreads();                   // all gathers of step t done
        s[k] = snew;
        sreg = snew;
        xv = xn;
        __syncthreads();                   // new state visible
    }

    finalst[b * DRES + r * SRES + k] = sreg;
}

// ============================================================================
// RMSNorm epilogue
// ============================================================================
__global__ __launch_bounds__(256) void rmsnorm_kernel(
    const float* __restrict__ hs, const float* __restrict__ ot,
    const float* __restrict__ lnw, float* __restrict__ y)
{
    __shared__ float red[8];
    int row = blockIdx.x, tid = threadIdx.x;
    const float4* h4 = (const float4*)(hs + (size_t)row * HID);
    const float4* o4 = (const float4*)(ot + (size_t)row * HID);
    const float4* l4 = (const float4*)lnw;
    float4* y4 = (float4*)(y + (size_t)row * HID);

    float4 v[2];
    float ss = 0.f;
    #pragma unroll
    for (int i = 0; i < 2; i++) {
        int idx = tid + i * 256;
        float4 a = h4[idx], b = o4[idx];
        float4 s = make_float4(a.x + b.x, a.y + b.y, a.z + b.z, a.w + b.w);
        v[i] = s;
        ss += s.x * s.x + s.y * s.y + s.z * s.z + s.w * s.w;
    }
    #pragma unroll
    for (int off = 16; off; off >>= 1) ss += __shfl_xor_sync(0xffffffffu, ss, off);
    if ((tid & 31) == 0) red[tid >> 5] = ss;
    __syncthreads();
    float tot = 0.f;
    #pragma unroll
    for (int i = 0; i < 8; i++) tot += red[i];
    float scale = rsqrtf(tot * (1.0f / HID) + 1e-6f);
    #pragma unroll
    for (int i = 0; i < 2; i++) {
        int idx = tid + i * 256;
        float4 lw = l4[idx];
        float4 s = v[i];
        y4[idx] = make_float4(s.x * scale * lw.x, s.y * scale * lw.y,
                              s.z * scale * lw.z, s.w * scale * lw.w);
    }
}

__global__ void copy_final_kernel(float* __restrict__ dst) {
    int i = blockIdx.x * 256 + threadIdx.x;
    if (i < BB * DRES) dst[i] = g_final[i];
}

// ============================================================================
extern "C" void kernel_launch(void* const* d_in, const int* in_sizes, int n_in,
                              void* d_out, int out_size)
{
    const float* hs   = (const float*)d_in[0];
    const float* prev = (const float*)d_in[1];
    const float* w_in = (const float*)d_in[2];
    const float* b_in = (const float*)d_in[3];
    const float* wres = (const float*)d_in[4];
    const float* wout = (const float*)d_in[5];
    const float* bout = (const float*)d_in[6];
    const float* lnw  = (const float*)d_in[7];
    float* out = (float*)d_out;

    void *px, *ps, *po, *pf;
    cudaGetSymbolAddress(&px, g_x);
    cudaGetSymbolAddress(&ps, g_states);
    cudaGetSymbolAddress(&po, g_out);
    cudaGetSymbolAddress(&pf, g_final);
    float* gx = (float*)px;
    float* gs = (float*)ps;
    float* go = (float*)po;
    float* gf = (float*)pf;

    static bool attr_set = false;
    if (!attr_set) {
        cudaFuncSetAttribute(gemm_tf32_kernel,
                             cudaFuncAttributeMaxDynamicSharedMemorySize,
                             GEMM_SMEM_BYTES);
        attr_set = true;
    }

    // 0) bank-scheduled sparse compression
    build_sparse_kernel<<<NRES, 256>>>(wres);

    // 1) x = hs @ w_in + b_in        [8192,1024]
    gemm_tf32_kernel<<<dim3(DRES / 128, MROWS / 128), 256, GEMM_SMEM_BYTES>>>(
        hs, w_in, b_in, gx, MROWS, DRES, HID);

    // 2) sparse reservoir scan -> states, final
    scan_sparse_kernel<<<16, 256>>>(gx, prev, gs, gf);

    // 3) out = states @ w_out + b_out  [8192,2048]
    gemm_tf32_kernel<<<dim3(HID / 128, MROWS / 128), 256, GEMM_SMEM_BYTES>>>(
        gs, wout, bout, go, MROWS, HID, DRES);

    // 4) y = RMSNorm(hs + out) * ln_w
    rmsnorm_kernel<<<MROWS, 256>>>(hs, go, lnw, out);

    // 5) final state appended after y (if the output buffer carries it)
    if (out_size >= MROWS * HID + BB * DRES) {
        float* fdst = out + (out_size - BB * DRES);
        copy_final_kernel<<<(BB * DRES + 255) / 256, 256>>>(fdst);
    }
}

// round 13
// speedup vs baseline: 1.6516x; 1.0112x over previous
#include <cuda_runtime.h>
#include <cstdint>
#include <math.h>

#define HID   2048
#define DRES  1024
#define NRES  4
#define SRES  256
#define BB    4
#define TT    2048
#define MROWS (BB*TT)
#define LEAK  0.1f
#define SPCAP 64          // slot-position capacity (true max nnz ~44 @ p=0.1)

// -------- scratch (static device globals; no allocation in kernel_launch) ----
__device__ float g_x[(size_t)MROWS * DRES];       // input projection  [8192,1024]
__device__ float g_states[(size_t)MROWS * DRES];  // reservoir states  [8192,1024]
__device__ float g_out[(size_t)MROWS * HID];      // output projection [8192,2048]
__device__ float g_final[BB * DRES];              // final state       [4,1024]
__device__ float    g_spv[NRES][SPCAP][SRES];     // sparse values  [r][slot][row]
__device__ uint32_t g_spo[NRES][SPCAP][SRES];     // byte offsets   [r][slot][row]
__device__ int      g_spn[NRES][8];               // padded slot count per warp (x8)

// ============================================================================
// tf32 mma.sync GEMM, 3-stage cp.async pipeline (validated: 285us per call)
// ============================================================================
__device__ __forceinline__ uint32_t f2tf32(float f) {
    uint32_t r; asm("cvt.rna.tf32.f32 %0, %1;" : "=r"(r) : "f"(f)); return r;
}

#define AS_STRIDE 36
#define BS_STRIDE 132
#define A_STAGE   (128 * AS_STRIDE)
#define B_STAGE   (32  * BS_STRIDE)
#define NSTAGE    3
#define GEMM_SMEM_BYTES ((NSTAGE * (A_STAGE + B_STAGE)) * 4)

#define CP_ASYNC_CG(dst, src) \
    asm volatile("cp.async.cg.shared.global [%0], [%1], 16;" :: "r"(dst), "l"(src))
#define CP_COMMIT() asm volatile("cp.async.commit_group;")
#define CP_WAIT1()  asm volatile("cp.async.wait_group 1;")

__global__ __launch_bounds__(256) void gemm_tf32_kernel(
    const float* __restrict__ A, const float* __restrict__ Bm,
    const float* __restrict__ bias, float* __restrict__ C,
    int M, int N, int K)
{
    extern __shared__ float smem[];
    float* As = smem;
    float* Bs = smem + NSTAGE * A_STAGE;
    uint32_t smA = (uint32_t)__cvta_generic_to_shared(As);
    uint32_t smB = (uint32_t)__cvta_generic_to_shared(Bs);

    int tid = threadIdx.x;
    int wid = tid >> 5, lane = tid & 31;
    int g = lane >> 2, tig = lane & 3;
    int m0 = blockIdx.y * 128, n0 = blockIdx.x * 128;
    int wm = (wid >> 1) * 32;
    int wn = (wid & 1) * 64;

    int arow[4], aquad[4], brow[4], bquad[4];
    #pragma unroll
    for (int i = 0; i < 4; i++) {
        int v = tid + i * 256;
        arow[i] = v >> 3;  aquad[i] = (v & 7)  << 2;
        brow[i] = v >> 5;  bquad[i] = (v & 31) << 2;
    }

    float acc[2][8][4];
    #pragma unroll
    for (int i = 0; i < 2; i++)
        #pragma unroll
        for (int j = 0; j < 8; j++)
            #pragma unroll
            for (int k = 0; k < 4; k++) acc[i][j][k] = 0.f;

    const int NK = K >> 5;

    #pragma unroll
    for (int s = 0; s < 2; s++) {
        int k0 = s * 32;
        #pragma unroll
        for (int i = 0; i < 4; i++) {
            const float* srcA = A + (size_t)(m0 + arow[i]) * K + k0 + aquad[i];
            CP_ASYNC_CG(smA + (uint32_t)((s * A_STAGE + arow[i] * AS_STRIDE + aquad[i]) * 4), srcA);
            const float* srcB = Bm + (size_t)(k0 + brow[i]) * N + n0 + bquad[i];
            CP_ASYNC_CG(smB + (uint32_t)((s * B_STAGE + brow[i] * BS_STRIDE + bquad[i]) * 4), srcB);
        }
        CP_COMMIT();
    }

    for (int it = 0; it < NK; it++) {
        CP_WAIT1();
        __syncthreads();

        if (it + 2 < NK) {
            int s = (it + 2) % NSTAGE;
            int k0 = (it + 2) << 5;
            #pragma unroll
            for (int i = 0; i < 4; i++) {
                const float* srcA = A + (size_t)(m0 + arow[i]) * K + k0 + aquad[i];
                CP_ASYNC_CG(smA + (uint32_t)((s * A_STAGE + arow[i] * AS_STRIDE + aquad[i]) * 4), srcA);
                const float* srcB = Bm + (size_t)(k0 + brow[i]) * N + n0 + bquad[i];
                CP_ASYNC_CG(smB + (uint32_t)((s * B_STAGE + brow[i] * BS_STRIDE + bquad[i]) * 4), srcB);
            }
        }
        CP_COMMIT();

        const float* as = As + (it % NSTAGE) * A_STAGE;
        const float* bs = Bs + (it % NSTAGE) * B_STAGE;
        #pragma unroll
        for (int ks = 0; ks < 32; ks += 8) {
            uint32_t af[2][4];
            #pragma unroll
            for (int tm = 0; tm < 2; tm++) {
                int rb = wm + tm * 16 + g;
                af[tm][0] = f2tf32(as[(rb     ) * AS_STRIDE + ks     + tig]);
                af[tm][1] = f2tf32(as[(rb +  8) * AS_STRIDE + ks     + tig]);
                af[tm][2] = f2tf32(as[(rb     ) * AS_STRIDE + ks + 4 + tig]);
                af[tm][3] = f2tf32(as[(rb +  8) * AS_STRIDE + ks + 4 + tig]);
            }
            uint32_t bf[8][2];
            #pragma unroll
            for (int tn = 0; tn < 8; tn++) {
                int col = wn + tn * 8 + g;
                bf[tn][0] = f2tf32(bs[(ks     + tig) * BS_STRIDE + col]);
                bf[tn][1] = f2tf32(bs[(ks + 4 + tig) * BS_STRIDE + col]);
            }
            #pragma unroll
            for (int tm = 0; tm < 2; tm++)
                #pragma unroll
                for (int tn = 0; tn < 8; tn++) {
                    asm volatile(
                        "mma.sync.aligned.m16n8k8.row.col.f32.tf32.tf32.f32 "
                        "{%0,%1,%2,%3}, {%4,%5,%6,%7}, {%8,%9}, {%0,%1,%2,%3};"
                        : "+f"(acc[tm][tn][0]), "+f"(acc[tm][tn][1]),
                          "+f"(acc[tm][tn][2]), "+f"(acc[tm][tn][3])
                        : "r"(af[tm][0]), "r"(af[tm][1]), "r"(af[tm][2]), "r"(af[tm][3]),
                          "r"(bf[tn][0]), "r"(bf[tn][1]));
                }
        }
    }

    #pragma unroll
    for (int tm = 0; tm < 2; tm++) {
        int row0 = m0 + wm + tm * 16 + g;
        #pragma unroll
        for (int tn = 0; tn < 8; tn++) {
            int col = n0 + wn + tn * 8 + tig * 2;
            float b0 = bias[col], b1 = bias[col + 1];
            float2 v0 = make_float2(acc[tm][tn][0] + b0, acc[tm][tn][1] + b1);
            float2 v1 = make_float2(acc[tm][tn][2] + b0, acc[tm][tn][3] + b1);
            *(float2*)(C + (size_t)row0 * N + col) = v0;
            *(float2*)(C + (size_t)(row0 + 8) * N + col) = v1;
        }
    }
}

// ============================================================================
// Bank-scheduled sparse compression of w_res (validated; np rounded to x8)
// ============================================================================
__global__ __launch_bounds__(256) void build_sparse_kernel(const float* __restrict__ wres)
{
    __shared__ unsigned long long bankused[8][32];  // [warp][bank] -> position mask
    __shared__ unsigned long long rmask[256];       // per-row placed-position mask
    __shared__ int maxpos_s[8];
    __shared__ uint32_t padw_s[8][SPCAP];           // pad bank per (warp, position)

    int r = blockIdx.x;
    int k = threadIdx.x;            // row
    int w = k >> 5, lane = k & 31;

    if (lane == 0) maxpos_s[w] = -1;
    bankused[w][lane] = 0ull;
    rmask[k] = 0ull;

    // phase 1: compact my row's nonzeros
    int jlist[SPCAP]; float vlist[SPCAP];
    int cnt = 0;
    const float* rowp = wres + ((size_t)(r * SRES + k)) * SRES;
    for (int j = 0; j < SRES; j++) {
        float wv = rowp[j];
        if (wv != 0.0f && cnt < SPCAP) { jlist[cnt] = j; vlist[cnt] = wv; cnt++; }
    }
    __syncthreads();

    // phase 2: serialized placement within each warp (lanes take turns)
    for (int l = 0; l < 32; l++) {
        if (lane == l) {
            unsigned long long rm = 0ull;
            int mp = maxpos_s[w];
            for (int i = 0; i < cnt; i++) {
                int bank = jlist[i] & 31;
                unsigned long long blocked = bankused[w][bank] | rm;
                unsigned long long freeM = ~blocked;
                int pos;
                if (freeM != 0ull) pos = __ffsll((long long)freeM) - 1;
                else {
                    unsigned long long f2 = ~rm;
                    if (f2 == 0ull) continue;             // row full (impossible)
                    pos = __ffsll((long long)f2) - 1;
                }
                if (pos < 0 || pos >= SPCAP) continue;
                bankused[w][bank] |= 1ull << pos;
                rm |= 1ull << pos;
                g_spv[r][pos][k] = vlist[i];
                g_spo[r][pos][k] = (uint32_t)(jlist[i] * 4);
                if (pos > mp) mp = pos;
            }
            rmask[k] = rm;
            maxpos_s[w] = mp;
        }
        __syncwarp();
    }
    __syncthreads();

    int np = ((maxpos_s[w] + 1) + 7) & ~7;     // multiple of 8 (gather group size)
    if (np < 8) np = 8;
    if (np > SPCAP) np = SPCAP;

    // phase 3a: pick a pad bank (free bank) for each (warp, position)
    for (int p = lane; p < SPCAP; p += 32) {
        uint32_t usedbanks = 0;
        #pragma unroll
        for (int bk = 0; bk < 32; bk++)
            usedbanks |= (uint32_t)((bankused[w][bk] >> p) & 1ull) << bk;
        uint32_t freeb = ~usedbanks;
        padw_s[w][p] = freeb ? (uint32_t)(__ffs(freeb) - 1) : 0u;
    }
    __syncthreads();

    // phase 3b: fill pads for every position this row didn't use
    unsigned long long rm = rmask[k];
    for (int p = 0; p < SPCAP; p++) {
        if (!((rm >> p) & 1ull)) {
            g_spv[r][p][k] = 0.0f;
            g_spo[r][p][k] = padw_s[w][p] * 4u;
        }
    }
    if (lane == 0) g_spn[r][w] = np;
}

// ============================================================================
// Sparse reservoir scan v2: double-buffered state (1 syncthreads/step),
// 8-wide load batches, second buffer addressed by +1024 immediate.
// ============================================================================
__device__ __forceinline__ float fast_tanh(float x) {
    return 1.0f - 2.0f / (__expf(2.0f * x) + 1.0f);
}

#define LDS_B0(dst, a) asm volatile("ld.shared.f32 %0, [%1];"      : "=f"(dst) : "r"(a))
#define LDS_B1(dst, a) asm volatile("ld.shared.f32 %0, [%1+1024];" : "=f"(dst) : "r"(a))

// one gather over a buffer: 8 LDS batched, then 8 FMAs
#define GATHER(LDSOP)                                                          \
    {                                                                          \
        a0 = 0.f; a1 = 0.f; a2 = 0.f; a3 = 0.f;                                \
        _Pragma("unroll")                                                      \
        for (int i = 0; i < SPCAP; i += 8) {                                   \
            if (i >= nslots) break;  /* warp-uniform */                        \
            float t0, t1, t2, t3, t4, t5, t6, t7;                              \
            LDSOP(t0, adr[i    ]); LDSOP(t1, adr[i + 1]);                      \
            LDSOP(t2, adr[i + 2]); LDSOP(t3, adr[i + 3]);                      \
            LDSOP(t4, adr[i + 4]); LDSOP(t5, adr[i + 5]);                      \
            LDSOP(t6, adr[i + 6]); LDSOP(t7, adr[i + 7]);                      \
            a0 = fmaf(val[i    ], t0, a0); a1 = fmaf(val[i + 1], t1, a1);      \
            a2 = fmaf(val[i + 2], t2, a2); a3 = fmaf(val[i + 3], t3, a3);      \
            a0 = fmaf(val[i + 4], t4, a0); a1 = fmaf(val[i + 5], t5, a1);      \
            a2 = fmaf(val[i + 6], t6, a2); a3 = fmaf(val[i + 7], t7, a3);      \
        }                                                                      \
    }

__global__ __launch_bounds__(256) void scan_sparse_kernel(
    const float* __restrict__ xin, const float* __restrict__ prev,
    float* __restrict__ states, float* __restrict__ finalst)
{
    __shared__ float s[2][SRES];     // buffer 1 sits exactly +1024 bytes

    int chain = blockIdx.x;          // 0..15
    int b = chain >> 2, r = chain & 3;
    int k = threadIdx.x;             // row 0..255
    uint32_t sbase = (uint32_t)__cvta_generic_to_shared(&s[0][0]);

    const int nslots = g_spn[r][k >> 5];   // uniform within warp, multiple of 8

    float    val[SPCAP];
    uint32_t adr[SPCAP];
    #pragma unroll
    for (int i = 0; i < SPCAP; i++) {
        val[i] = g_spv[r][i][k];
        adr[i] = g_spo[r][i][k] + sbase;   // buffer-0 address; buffer 1 = +1024 imm
    }

    float sreg = prev[b * DRES + r * SRES + k];
    s[0][k] = sreg;

    const float* xp = xin    + (size_t)b * TT * DRES + r * SRES + k;
    float*       sp = states + (size_t)b * TT * DRES + r * SRES + k;
    float xv = xp[0];
    __syncthreads();

    float a0, a1, a2, a3;
    for (int t = 0; t < TT; t += 2) {
        // ---- step t: read s[0], write s[1] ----
        float xn1 = xp[(size_t)(t + 1) * DRES];     // t+1 < TT always (TT even)
        GATHER(LDS_B0);
        {
            float pre  = (a0 + a1) + (a2 + a3) + xv;
            float snew = (1.0f - LEAK) * sreg + LEAK * fast_tanh(pre);
            sp[(size_t)t * DRES] = snew;
            s[1][k] = snew;
            sreg = snew;
            xv = xn1;
        }
        __syncthreads();   // s[1] visible; everyone done reading s[0]

        // ---- step t+1: read s[1], write s[0] ----
        float xn2 = (t + 2 < TT) ? xp[(size_t)(t + 2) * DRES] : 0.f;
        GATHER(LDS_B1);
        {
            float pre  = (a0 + a1) + (a2 + a3) + xv;
            float snew = (1.0f - LEAK) * sreg + LEAK * fast_tanh(pre);
            sp[(size_t)(t + 1) * DRES] = snew;
            s[0][k] = snew;
            sreg = snew;
            xv = xn2;
        }
        __syncthreads();   // s[0] visible; everyone done reading s[1]
    }

    finalst[b * DRES + r * SRES + k] = sreg;
}

// ============================================================================
// RMSNorm epilogue
// ============================================================================
__global__ __launch_bounds__(256) void rmsnorm_kernel(
    const float* __restrict__ hs, const float* __restrict__ ot,
    const float* __restrict__ lnw, float* __restrict__ y)
{
    __shared__ float red[8];
    int row = blockIdx.x, tid = threadIdx.x;
    const float4* h4 = (const float4*)(hs + (size_t)row * HID);
    const float4* o4 = (const float4*)(ot + (size_t)row * HID);
    const float4* l4 = (const float4*)lnw;
    float4* y4 = (float4*)(y + (size_t)row * HID);

    float4 v[2];
    float ss = 0.f;
    #pragma unroll
    for (int i = 0; i < 2; i++) {
        int idx = tid + i * 256;
        float4 a = h4[idx], b = o4[idx];
        float4 s = make_float4(a.x + b.x, a.y + b.y, a.z + b.z, a.w + b.w);
        v[i] = s;
        ss += s.x * s.x + s.y * s.y + s.z * s.z + s.w * s.w;
    }
    #pragma unroll
    for (int off = 16; off; off >>= 1) ss += __shfl_xor_sync(0xffffffffu, ss, off);
    if ((tid & 31) == 0) red[tid >> 5] = ss;
    __syncthreads();
    float tot = 0.f;
    #pragma unroll
    for (int i = 0; i < 8; i++) tot += red[i];
    float scale = rsqrtf(tot * (1.0f / HID) + 1e-6f);
    #pragma unroll
    for (int i = 0; i < 2; i++) {
        int idx = tid + i * 256;
        float4 lw = l4[idx];
        float4 s = v[i];
        y4[idx] = make_float4(s.x * scale * lw.x, s.y * scale * lw.y,
                              s.z * scale * lw.z, s.w * scale * lw.w);
    }
}

__global__ void copy_final_kernel(float* __restrict__ dst) {
    int i = blockIdx.x * 256 + threadIdx.x;
    if (i < BB * DRES) dst[i] = g_final[i];
}

// ============================================================================
extern "C" void kernel_launch(void* const* d_in, const int* in_sizes, int n_in,
                              void* d_out, int out_size)
{
    const float* hs   = (const float*)d_in[0];
    const float* prev = (const float*)d_in[1];
    const float* w_in = (const float*)d_in[2];
    const float* b_in = (const float*)d_in[3];
    const float* wres = (const float*)d_in[4];
    const float* wout = (const float*)d_in[5];
    const float* bout = (const float*)d_in[6];
    const float* lnw  = (const float*)d_in[7];
    float* out = (float*)d_out;

    void *px, *ps, *po, *pf;
    cudaGetSymbolAddress(&px, g_x);
    cudaGetSymbolAddress(&ps, g_states);
    cudaGetSymbolAddress(&po, g_out);
    cudaGetSymbolAddress(&pf, g_final);
    float* gx = (float*)px;
    float* gs = (float*)ps;
    float* go = (float*)po;
    float* gf = (float*)pf;

    static bool attr_set = false;
    if (!attr_set) {
        cudaFuncSetAttribute(gemm_tf32_kernel,
                             cudaFuncAttributeMaxDynamicSharedMemorySize,
                             GEMM_SMEM_BYTES);
        attr_set = true;
    }

    // 0) bank-scheduled sparse compression
    build_sparse_kernel<<<NRES, 256>>>(wres);

    // 1) x = hs @ w_in + b_in        [8192,1024]
    gemm_tf32_kernel<<<dim3(DRES / 128, MROWS / 128), 256, GEMM_SMEM_BYTES>>>(
        hs, w_in, b_in, gx, MROWS, DRES, HID);

    // 2) sparse reservoir scan -> states, final
    scan_sparse_kernel<<<16, 256>>>(gx, prev, gs, gf);

    // 3) out = states @ w_out + b_out  [8192,2048]
    gemm_tf32_kernel<<<dim3(HID / 128, MROWS / 128), 256, GEMM_SMEM_BYTES>>>(
        gs, wout, bout, go, MROWS, HID, DRES);

    // 4) y = RMSNorm(hs + out) * ln_w
    rmsnorm_kernel<<<MROWS, 256>>>(hs, go, lnw, out);

    // 5) final state appended after y (if the output buffer carries it)
    if (out_size >= MROWS * HID + BB * DRES) {
        float* fdst = out + (out_size - BB * DRES);
        copy_final_kernel<<<(BB * DRES + 255) / 256, 256>>>(fdst);
    }
}

// round 14
// speedup vs baseline: 1.8966x; 1.1483x over previous
#include <cuda_runtime.h>
#include <cstdint>
#include <math.h>

#define HID   2048
#define DRES  1024
#define NRES  4
#define SRES  256
#define BB    4
#define TT    2048
#define MROWS (BB*TT)
#define LEAK  0.1f
#define SPCAP 64          // slot-position capacity (true max nnz ~44 @ p=0.1)
#define XROWS 8           // timesteps per x-prefetch batch
#define NBLK  (TT / XROWS)

// -------- scratch (static device globals; no allocation in kernel_launch) ----
__device__ float g_x[(size_t)MROWS * DRES];       // input projection  [8192,1024]
__device__ float g_states[(size_t)MROWS * DRES];  // reservoir states  [8192,1024]
__device__ float g_out[(size_t)MROWS * HID];      // output projection [8192,2048]
__device__ float g_final[BB * DRES];              // final state       [4,1024]
__device__ float    g_spv[NRES][SPCAP][SRES];     // sparse values  [r][slot][row]
__device__ uint32_t g_spo[NRES][SPCAP][SRES];     // byte offsets   [r][slot][row]
__device__ int      g_spn[NRES][8];               // padded slot count per warp (x8)

// ============================================================================
// tf32 mma.sync GEMM, 3-stage cp.async pipeline (validated: 285us per call)
// ============================================================================
__device__ __forceinline__ uint32_t f2tf32(float f) {
    uint32_t r; asm("cvt.rna.tf32.f32 %0, %1;" : "=r"(r) : "f"(f)); return r;
}

#define AS_STRIDE 36
#define BS_STRIDE 132
#define A_STAGE   (128 * AS_STRIDE)
#define B_STAGE   (32  * BS_STRIDE)
#define NSTAGE    3
#define GEMM_SMEM_BYTES ((NSTAGE * (A_STAGE + B_STAGE)) * 4)

#define CP_ASYNC_CG(dst, src) \
    asm volatile("cp.async.cg.shared.global [%0], [%1], 16;" :: "r"(dst), "l"(src))
#define CP_ASYNC_CA16(dst, src) \
    asm volatile("cp.async.ca.shared.global [%0], [%1], 16;" :: "r"(dst), "l"(src))
#define CP_COMMIT() asm volatile("cp.async.commit_group;")
#define CP_WAIT1()  asm volatile("cp.async.wait_group 1;")

__global__ __launch_bounds__(256) void gemm_tf32_kernel(
    const float* __restrict__ A, const float* __restrict__ Bm,
    const float* __restrict__ bias, float* __restrict__ C,
    int M, int N, int K)
{
    extern __shared__ float smem[];
    float* As = smem;
    float* Bs = smem + NSTAGE * A_STAGE;
    uint32_t smA = (uint32_t)__cvta_generic_to_shared(As);
    uint32_t smB = (uint32_t)__cvta_generic_to_shared(Bs);

    int tid = threadIdx.x;
    int wid = tid >> 5, lane = tid & 31;
    int g = lane >> 2, tig = lane & 3;
    int m0 = blockIdx.y * 128, n0 = blockIdx.x * 128;
    int wm = (wid >> 1) * 32;
    int wn = (wid & 1) * 64;

    int arow[4], aquad[4], brow[4], bquad[4];
    #pragma unroll
    for (int i = 0; i < 4; i++) {
        int v = tid + i * 256;
        arow[i] = v >> 3;  aquad[i] = (v & 7)  << 2;
        brow[i] = v >> 5;  bquad[i] = (v & 31) << 2;
    }

    float acc[2][8][4];
    #pragma unroll
    for (int i = 0; i < 2; i++)
        #pragma unroll
        for (int j = 0; j < 8; j++)
            #pragma unroll
            for (int k = 0; k < 4; k++) acc[i][j][k] = 0.f;

    const int NK = K >> 5;

    #pragma unroll
    for (int s = 0; s < 2; s++) {
        int k0 = s * 32;
        #pragma unroll
        for (int i = 0; i < 4; i++) {
            const float* srcA = A + (size_t)(m0 + arow[i]) * K + k0 + aquad[i];
            CP_ASYNC_CG(smA + (uint32_t)((s * A_STAGE + arow[i] * AS_STRIDE + aquad[i]) * 4), srcA);
            const float* srcB = Bm + (size_t)(k0 + brow[i]) * N + n0 + bquad[i];
            CP_ASYNC_CG(smB + (uint32_t)((s * B_STAGE + brow[i] * BS_STRIDE + bquad[i]) * 4), srcB);
        }
        CP_COMMIT();
    }

    for (int it = 0; it < NK; it++) {
        CP_WAIT1();
        __syncthreads();

        if (it + 2 < NK) {
            int s = (it + 2) % NSTAGE;
            int k0 = (it + 2) << 5;
            #pragma unroll
            for (int i = 0; i < 4; i++) {
                const float* srcA = A + (size_t)(m0 + arow[i]) * K + k0 + aquad[i];
                CP_ASYNC_CG(smA + (uint32_t)((s * A_STAGE + arow[i] * AS_STRIDE + aquad[i]) * 4), srcA);
                const float* srcB = Bm + (size_t)(k0 + brow[i]) * N + n0 + bquad[i];
                CP_ASYNC_CG(smB + (uint32_t)((s * B_STAGE + brow[i] * BS_STRIDE + bquad[i]) * 4), srcB);
            }
        }
        CP_COMMIT();

        const float* as = As + (it % NSTAGE) * A_STAGE;
        const float* bs = Bs + (it % NSTAGE) * B_STAGE;
        #pragma unroll
        for (int ks = 0; ks < 32; ks += 8) {
            uint32_t af[2][4];
            #pragma unroll
            for (int tm = 0; tm < 2; tm++) {
                int rb = wm + tm * 16 + g;
                af[tm][0] = f2tf32(as[(rb     ) * AS_STRIDE + ks     + tig]);
                af[tm][1] = f2tf32(as[(rb +  8) * AS_STRIDE + ks     + tig]);
                af[tm][2] = f2tf32(as[(rb     ) * AS_STRIDE + ks + 4 + tig]);
                af[tm][3] = f2tf32(as[(rb +  8) * AS_STRIDE + ks + 4 + tig]);
            }
            uint32_t bf[8][2];
            #pragma unroll
            for (int tn = 0; tn < 8; tn++) {
                int col = wn + tn * 8 + g;
                bf[tn][0] = f2tf32(bs[(ks     + tig) * BS_STRIDE + col]);
                bf[tn][1] = f2tf32(bs[(ks + 4 + tig) * BS_STRIDE + col]);
            }
            #pragma unroll
            for (int tm = 0; tm < 2; tm++)
                #pragma unroll
                for (int tn = 0; tn < 8; tn++) {
                    asm volatile(
                        "mma.sync.aligned.m16n8k8.row.col.f32.tf32.tf32.f32 "
                        "{%0,%1,%2,%3}, {%4,%5,%6,%7}, {%8,%9}, {%0,%1,%2,%3};"
                        : "+f"(acc[tm][tn][0]), "+f"(acc[tm][tn][1]),
                          "+f"(acc[tm][tn][2]), "+f"(acc[tm][tn][3])
                        : "r"(af[tm][0]), "r"(af[tm][1]), "r"(af[tm][2]), "r"(af[tm][3]),
                          "r"(bf[tn][0]), "r"(bf[tn][1]));
                }
        }
    }

    #pragma unroll
    for (int tm = 0; tm < 2; tm++) {
        int row0 = m0 + wm + tm * 16 + g;
        #pragma unroll
        for (int tn = 0; tn < 8; tn++) {
            int col = n0 + wn + tn * 8 + tig * 2;
            float b0 = bias[col], b1 = bias[col + 1];
            float2 v0 = make_float2(acc[tm][tn][0] + b0, acc[tm][tn][1] + b1);
            float2 v1 = make_float2(acc[tm][tn][2] + b0, acc[tm][tn][3] + b1);
            *(float2*)(C + (size_t)row0 * N + col) = v0;
            *(float2*)(C + (size_t)(row0 + 8) * N + col) = v1;
        }
    }
}

// ============================================================================
// Bank-scheduled sparse compression of w_res (validated; np rounded to x8)
// ============================================================================
__global__ __launch_bounds__(256) void build_sparse_kernel(const float* __restrict__ wres)
{
    __shared__ unsigned long long bankused[8][32];  // [warp][bank] -> position mask
    __shared__ unsigned long long rmask[256];       // per-row placed-position mask
    __shared__ int maxpos_s[8];
    __shared__ uint32_t padw_s[8][SPCAP];           // pad bank per (warp, position)

    int r = blockIdx.x;
    int k = threadIdx.x;            // row
    int w = k >> 5, lane = k & 31;

    if (lane == 0) maxpos_s[w] = -1;
    bankused[w][lane] = 0ull;
    rmask[k] = 0ull;

    // phase 1: compact my row's nonzeros
    int jlist[SPCAP]; float vlist[SPCAP];
    int cnt = 0;
    const float* rowp = wres + ((size_t)(r * SRES + k)) * SRES;
    for (int j = 0; j < SRES; j++) {
        float wv = rowp[j];
        if (wv != 0.0f && cnt < SPCAP) { jlist[cnt] = j; vlist[cnt] = wv; cnt++; }
    }
    __syncthreads();

    // phase 2: serialized placement within each warp (lanes take turns)
    for (int l = 0; l < 32; l++) {
        if (lane == l) {
            unsigned long long rm = 0ull;
            int mp = maxpos_s[w];
            for (int i = 0; i < cnt; i++) {
                int bank = jlist[i] & 31;
                unsigned long long blocked = bankused[w][bank] | rm;
                unsigned long long freeM = ~blocked;
                int pos;
                if (freeM != 0ull) pos = __ffsll((long long)freeM) - 1;
                else {
                    unsigned long long f2 = ~rm;
                    if (f2 == 0ull) continue;             // row full (impossible)
                    pos = __ffsll((long long)f2) - 1;
                }
                if (pos < 0 || pos >= SPCAP) continue;
                bankused[w][bank] |= 1ull << pos;
                rm |= 1ull << pos;
                g_spv[r][pos][k] = vlist[i];
                g_spo[r][pos][k] = (uint32_t)(jlist[i] * 4);
                if (pos > mp) mp = pos;
            }
            rmask[k] = rm;
            maxpos_s[w] = mp;
        }
        __syncwarp();
    }
    __syncthreads();

    int np = ((maxpos_s[w] + 1) + 7) & ~7;     // multiple of 8 (gather group size)
    if (np < 8) np = 8;
    if (np > SPCAP) np = SPCAP;

    // phase 3a: pick a pad bank (free bank) for each (warp, position)
    for (int p = lane; p < SPCAP; p += 32) {
        uint32_t usedbanks = 0;
        #pragma unroll
        for (int bk = 0; bk < 32; bk++)
            usedbanks |= (uint32_t)((bankused[w][bk] >> p) & 1ull) << bk;
        uint32_t freeb = ~usedbanks;
        padw_s[w][p] = freeb ? (uint32_t)(__ffs(freeb) - 1) : 0u;
    }
    __syncthreads();

    // phase 3b: fill pads for every position this row didn't use
    unsigned long long rm = rmask[k];
    for (int p = 0; p < SPCAP; p++) {
        if (!((rm >> p) & 1ull)) {
            g_spv[r][p][k] = 0.0f;
            g_spo[r][p][k] = padw_s[w][p] * 4u;
        }
    }
    if (lane == 0) g_spn[r][w] = np;
}

// ============================================================================
// Sparse reservoir scan v3: x staged via cp.async in 8-step batches (latency
// decoupled); double-buffered state, 8-wide batched gathers.
// ============================================================================
__device__ __forceinline__ float fast_tanh(float x) {
    return 1.0f - 2.0f / (__expf(2.0f * x) + 1.0f);
}

#define LDS_B0(dst, a) asm volatile("ld.shared.f32 %0, [%1];"      : "=f"(dst) : "r"(a))
#define LDS_B1(dst, a) asm volatile("ld.shared.f32 %0, [%1+1024];" : "=f"(dst) : "r"(a))

// one gather over a buffer: 8 LDS batched, then 8 FMAs
#define GATHER(LDSOP)                                                          \
    {                                                                          \
        a0 = 0.f; a1 = 0.f; a2 = 0.f; a3 = 0.f;                                \
        _Pragma("unroll")                                                      \
        for (int i = 0; i < SPCAP; i += 8) {                                   \
            if (i >= nslots) break;  /* warp-uniform */                        \
            float t0, t1, t2, t3, t4, t5, t6, t7;                              \
            LDSOP(t0, adr[i    ]); LDSOP(t1, adr[i + 1]);                      \
            LDSOP(t2, adr[i + 2]); LDSOP(t3, adr[i + 3]);                      \
            LDSOP(t4, adr[i + 4]); LDSOP(t5, adr[i + 5]);                      \
            LDSOP(t6, adr[i + 6]); LDSOP(t7, adr[i + 7]);                      \
            a0 = fmaf(val[i    ], t0, a0); a1 = fmaf(val[i + 1], t1, a1);      \
            a2 = fmaf(val[i + 2], t2, a2); a3 = fmaf(val[i + 3], t3, a3);      \
            a0 = fmaf(val[i + 4], t4, a0); a1 = fmaf(val[i + 5], t5, a1);      \
            a2 = fmaf(val[i + 6], t6, a2); a3 = fmaf(val[i + 7], t7, a3);      \
        }                                                                      \
    }

__global__ __launch_bounds__(256) void scan_sparse_kernel(
    const float* __restrict__ xin, const float* __restrict__ prev,
    float* __restrict__ states, float* __restrict__ finalst)
{
    __shared__ float s[2][SRES];               // buffer 1 at +1024 bytes
    __shared__ float sx[2][XROWS][SRES];       // x staging: 2 x 8KB

    int chain = blockIdx.x;          // 0..15
    int b = chain >> 2, r = chain & 3;
    int k = threadIdx.x;             // row 0..255
    uint32_t sbase  = (uint32_t)__cvta_generic_to_shared(&s[0][0]);
    uint32_t sxbase = (uint32_t)__cvta_generic_to_shared(&sx[0][0][0]);

    const int nslots = g_spn[r][k >> 5];   // uniform within warp, multiple of 8

    float    val[SPCAP];
    uint32_t adr[SPCAP];
    #pragma unroll
    for (int i = 0; i < SPCAP; i++) {
        val[i] = g_spv[r][i][k];
        adr[i] = g_spo[r][i][k] + sbase;   // buffer-0 address; buffer 1 = +1024 imm
    }

    // x source base for this chain; batch bb covers t = bb*8 .. bb*8+7
    const float* xb0 = xin + (size_t)b * TT * DRES + r * SRES;
    int xrow = k >> 6;               // 0..3 (two rounds cover 8 rows)
    int xoff = (k & 63) << 2;        // float offset within 1KB row (16B per thread)

    // prologue: issue batches 0 and 1
    #pragma unroll
    for (int bb = 0; bb < 2; bb++) {
        #pragma unroll
        for (int rnd = 0; rnd < 2; rnd++) {
            int j = xrow + rnd * 4;
            const float* src = xb0 + (size_t)(bb * XROWS + j) * DRES + xoff;
            uint32_t dst = sxbase + (uint32_t)((bb * XROWS * SRES + j * SRES + xoff) * 4);
            CP_ASYNC_CA16(dst, src);
        }
        CP_COMMIT();
    }

    float sreg = prev[b * DRES + r * SRES + k];
    s[0][k] = sreg;

    float* sp = states + (size_t)b * TT * DRES + r * SRES + k;
    __syncthreads();

    float a0, a1, a2, a3;
    for (int tb = 0; tb < NBLK; tb++) {
        CP_WAIT1();          // batch tb landed (only newest group may pend)
        __syncthreads();     // visible to all threads
        int slot = tb & 1;

        #pragma unroll
        for (int u = 0; u < XROWS; u += 2) {
            // ---- step tb*8+u: read s[0], write s[1] ----
            float xv0 = sx[slot][u][k];
            GATHER(LDS_B0);
            {
                float pre  = (a0 + a1) + (a2 + a3) + xv0;
                float snew = (1.0f - LEAK) * sreg + LEAK * fast_tanh(pre);
                sp[(size_t)(tb * XROWS + u) * DRES] = snew;
                s[1][k] = snew;
                sreg = snew;
            }
            __syncthreads();

            // ---- step tb*8+u+1: read s[1], write s[0] ----
            float xv1 = sx[slot][u + 1][k];
            GATHER(LDS_B1);
            {
                float pre  = (a0 + a1) + (a2 + a3) + xv1;
                float snew = (1.0f - LEAK) * sreg + LEAK * fast_tanh(pre);
                sp[(size_t)(tb * XROWS + u + 1) * DRES] = snew;
                s[0][k] = snew;
                sreg = snew;
            }
            __syncthreads();
        }

        // issue batch tb+2 into slot (just freed); empty commit keeps counting
        if (tb + 2 < NBLK) {
            #pragma unroll
            for (int rnd = 0; rnd < 2; rnd++) {
                int j = xrow + rnd * 4;
                const float* src = xb0 + (size_t)((tb + 2) * XROWS + j) * DRES + xoff;
                uint32_t dst = sxbase + (uint32_t)((slot * XROWS * SRES + j * SRES + xoff) * 4);
                CP_ASYNC_CA16(dst, src);
            }
        }
        CP_COMMIT();
    }

    finalst[b * DRES + r * SRES + k] = sreg;
}

// ============================================================================
// RMSNorm epilogue
// ============================================================================
__global__ __launch_bounds__(256) void rmsnorm_kernel(
    const float* __restrict__ hs, const float* __restrict__ ot,
    const float* __restrict__ lnw, float* __restrict__ y)
{
    __shared__ float red[8];
    int row = blockIdx.x, tid = threadIdx.x;
    const float4* h4 = (const float4*)(hs + (size_t)row * HID);
    const float4* o4 = (const float4*)(ot + (size_t)row * HID);
    const float4* l4 = (const float4*)lnw;
    float4* y4 = (float4*)(y + (size_t)row * HID);

    float4 v[2];
    float ss = 0.f;
    #pragma unroll
    for (int i = 0; i < 2; i++) {
        int idx = tid + i * 256;
        float4 a = h4[idx], b = o4[idx];
        float4 s = make_float4(a.x + b.x, a.y + b.y, a.z + b.z, a.w + b.w);
        v[i] = s;
        ss += s.x * s.x + s.y * s.y + s.z * s.z + s.w * s.w;
    }
    #pragma unroll
    for (int off = 16; off; off >>= 1) ss += __shfl_xor_sync(0xffffffffu, ss, off);
    if ((tid & 31) == 0) red[tid >> 5] = ss;
    __syncthreads();
    float tot = 0.f;
    #pragma unroll
    for (int i = 0; i < 8; i++) tot += red[i];
    float scale = rsqrtf(tot * (1.0f / HID) + 1e-6f);
    #pragma unroll
    for (int i = 0; i < 2; i++) {
        int idx = tid + i * 256;
        float4 lw = l4[idx];
        float4 s = v[i];
        y4[idx] = make_float4(s.x * scale * lw.x, s.y * scale * lw.y,
                              s.z * scale * lw.z, s.w * scale * lw.w);
    }
}

__global__ void copy_final_kernel(float* __restrict__ dst) {
    int i = blockIdx.x * 256 + threadIdx.x;
    if (i < BB * DRES) dst[i] = g_final[i];
}

// ============================================================================
extern "C" void kernel_launch(void* const* d_in, const int* in_sizes, int n_in,
                              void* d_out, int out_size)
{
    const float* hs   = (const float*)d_in[0];
    const float* prev = (const float*)d_in[1];
    const float* w_in = (const float*)d_in[2];
    const float* b_in = (const float*)d_in[3];
    const float* wres = (const float*)d_in[4];
    const float* wout = (const float*)d_in[5];
    const float* bout = (const float*)d_in[6];
    const float* lnw  = (const float*)d_in[7];
    float* out = (float*)d_out;

    void *px, *ps, *po, *pf;
    cudaGetSymbolAddress(&px, g_x);
    cudaGetSymbolAddress(&ps, g_states);
    cudaGetSymbolAddress(&po, g_out);
    cudaGetSymbolAddress(&pf, g_final);
    float* gx = (float*)px;
    float* gs = (float*)ps;
    float* go = (float*)po;
    float* gf = (float*)pf;

    static bool attr_set = false;
    if (!attr_set) {
        cudaFuncSetAttribute(gemm_tf32_kernel,
                             cudaFuncAttributeMaxDynamicSharedMemorySize,
                             GEMM_SMEM_BYTES);
        attr_set = true;
    }

    // 0) bank-scheduled sparse compression
    build_sparse_kernel<<<NRES, 256>>>(wres);

    // 1) x = hs @ w_in + b_in        [8192,1024]
    gemm_tf32_kernel<<<dim3(DRES / 128, MROWS / 128), 256, GEMM_SMEM_BYTES>>>(
        hs, w_in, b_in, gx, MROWS, DRES, HID);

    // 2) sparse reservoir scan -> states, final
    scan_sparse_kernel<<<16, 256>>>(gx, prev, gs, gf);

    // 3) out = states @ w_out + b_out  [8192,2048]
    gemm_tf32_kernel<<<dim3(HID / 128, MROWS / 128), 256, GEMM_SMEM_BYTES>>>(
        gs, wout, bout, go, MROWS, HID, DRES);

    // 4) y = RMSNorm(hs + out) * ln_w
    rmsnorm_kernel<<<MROWS, 256>>>(hs, go, lnw, out);

    // 5) final state appended after y (if the output buffer carries it)
    if (out_size >= MROWS * HID + BB * DRES) {
        float* fdst = out + (out_size - BB * DRES);
        copy_final_kernel<<<(BB * DRES + 255) / 256, 256>>>(fdst);
    }
}

// round 17
// speedup vs baseline: 2.6028x; 1.3724x over previous
#include <cuda_runtime.h>
#include <cstdint>
#include <math.h>

#define HID   2048
#define DRES  1024
#define NRES  4
#define SRES  256
#define BB    4
#define TT    2048
#define MROWS (BB*TT)
#define LEAK  0.1f
#define SPCAP 64          // slot-position capacity (true max nnz ~44 @ p=0.1)
#define XROWS 8           // timesteps per x-prefetch batch
#define NBLK  (TT / XROWS)

#define NSCAN   16                    // scan blocks (one per chain)
#define NWORK   132                   // worker blocks
#define NGRID   (NSCAN + NWORK)       // 148 = all resident, no deadlock
#define NT1     512                   // gemm1 tiles: 16 tblk x 4 b x 8 n
#define NT2     1024                  // gemm2 tiles: 16 tblk x 4 b x 16 n
#define NTILES  (NT1 + NT2)

// -------- scratch (static device globals; no allocation in kernel_launch) ----
__device__ float g_x[(size_t)MROWS * DRES];       // input projection  [8192,1024]
__device__ float g_states[(size_t)MROWS * DRES];  // reservoir states  [8192,1024]
__device__ float g_out[(size_t)MROWS * HID];      // output projection [8192,2048]
__device__ float g_final[BB * DRES];              // final state       [4,1024]
__device__ float    g_spv[NRES][SPCAP][SRES];     // sparse values  [r][slot][row]
__device__ uint32_t g_spo[NRES][SPCAP][SRES];     // byte offsets   [r][slot][row]
__device__ int      g_spn[NRES][8];               // padded slot count per warp (x8)
__device__ int      g_f1[BB * 16];                // gemm1 done-count per (b,tblk), need 8
__device__ int      g_f2[BB * 16];                // scan done-count per (b,tblk), need 4
__device__ int      g_tilectr;                    // worker tile queue head

// ============================================================================
// tf32 mma.sync GEMM tile (device function; body identical to validated kernel)
// ============================================================================
__device__ __forceinline__ uint32_t f2tf32(float f) {
    uint32_t r; asm("cvt.rna.tf32.f32 %0, %1;" : "=r"(r) : "f"(f)); return r;
}

#define AS_STRIDE 36
#define BS_STRIDE 132
#define A_STAGE   (128 * AS_STRIDE)
#define B_STAGE   (32  * BS_STRIDE)
#define NSTAGE    3
#define GEMM_SMEM_BYTES ((NSTAGE * (A_STAGE + B_STAGE)) * 4)

#define CP_ASYNC_CG(dst, src) \
    asm volatile("cp.async.cg.shared.global [%0], [%1], 16;" :: "r"(dst), "l"(src))
#define CP_ASYNC_CA16(dst, src) \
    asm volatile("cp.async.ca.shared.global [%0], [%1], 16;" :: "r"(dst), "l"(src))
#define CP_COMMIT() asm volatile("cp.async.commit_group;")
#define CP_WAIT1()  asm volatile("cp.async.wait_group 1;")

__device__ void gemm_tile(const float* __restrict__ A, const float* __restrict__ Bm,
                          const float* __restrict__ bias, float* __restrict__ C,
                          int N, int K, int m0, int n0, float* smem)
{
    float* As = smem;
    float* Bs = smem + NSTAGE * A_STAGE;
    uint32_t smA = (uint32_t)__cvta_generic_to_shared(As);
    uint32_t smB = (uint32_t)__cvta_generic_to_shared(Bs);

    int tid = threadIdx.x;
    int wid = tid >> 5, lane = tid & 31;
    int g = lane >> 2, tig = lane & 3;
    int wm = (wid >> 1) * 32;
    int wn = (wid & 1) * 64;

    int arow[4], aquad[4], brow[4], bquad[4];
    #pragma unroll
    for (int i = 0; i < 4; i++) {
        int v = tid + i * 256;
        arow[i] = v >> 3;  aquad[i] = (v & 7)  << 2;
        brow[i] = v >> 5;  bquad[i] = (v & 31) << 2;
    }

    float acc[2][8][4];
    #pragma unroll
    for (int i = 0; i < 2; i++)
        #pragma unroll
        for (int j = 0; j < 8; j++)
            #pragma unroll
            for (int k = 0; k < 4; k++) acc[i][j][k] = 0.f;

    const int NK = K >> 5;

    #pragma unroll
    for (int s = 0; s < 2; s++) {
        int k0 = s * 32;
        #pragma unroll
        for (int i = 0; i < 4; i++) {
            const float* srcA = A + (size_t)(m0 + arow[i]) * K + k0 + aquad[i];
            CP_ASYNC_CG(smA + (uint32_t)((s * A_STAGE + arow[i] * AS_STRIDE + aquad[i]) * 4), srcA);
            const float* srcB = Bm + (size_t)(k0 + brow[i]) * N + n0 + bquad[i];
            CP_ASYNC_CG(smB + (uint32_t)((s * B_STAGE + brow[i] * BS_STRIDE + bquad[i]) * 4), srcB);
        }
        CP_COMMIT();
    }

    for (int it = 0; it < NK; it++) {
        CP_WAIT1();
        __syncthreads();

        if (it + 2 < NK) {
            int s = (it + 2) % NSTAGE;
            int k0 = (it + 2) << 5;
            #pragma unroll
            for (int i = 0; i < 4; i++) {
                const float* srcA = A + (size_t)(m0 + arow[i]) * K + k0 + aquad[i];
                CP_ASYNC_CG(smA + (uint32_t)((s * A_STAGE + arow[i] * AS_STRIDE + aquad[i]) * 4), srcA);
                const float* srcB = Bm + (size_t)(k0 + brow[i]) * N + n0 + bquad[i];
                CP_ASYNC_CG(smB + (uint32_t)((s * B_STAGE + brow[i] * BS_STRIDE + bquad[i]) * 4), srcB);
            }
        }
        CP_COMMIT();

        const float* as = As + (it % NSTAGE) * A_STAGE;
        const float* bs = Bs + (it % NSTAGE) * B_STAGE;
        #pragma unroll
        for (int ks = 0; ks < 32; ks += 8) {
            uint32_t af[2][4];
            #pragma unroll
            for (int tm = 0; tm < 2; tm++) {
                int rb = wm + tm * 16 + g;
                af[tm][0] = f2tf32(as[(rb     ) * AS_STRIDE + ks     + tig]);
                af[tm][1] = f2tf32(as[(rb +  8) * AS_STRIDE + ks     + tig]);
                af[tm][2] = f2tf32(as[(rb     ) * AS_STRIDE + ks + 4 + tig]);
                af[tm][3] = f2tf32(as[(rb +  8) * AS_STRIDE + ks + 4 + tig]);
            }
            uint32_t bf[8][2];
            #pragma unroll
            for (int tn = 0; tn < 8; tn++) {
                int col = wn + tn * 8 + g;
                bf[tn][0] = f2tf32(bs[(ks     + tig) * BS_STRIDE + col]);
                bf[tn][1] = f2tf32(bs[(ks + 4 + tig) * BS_STRIDE + col]);
            }
            #pragma unroll
            for (int tm = 0; tm < 2; tm++)
                #pragma unroll
                for (int tn = 0; tn < 8; tn++) {
                    asm volatile(
                        "mma.sync.aligned.m16n8k8.row.col.f32.tf32.tf32.f32 "
                        "{%0,%1,%2,%3}, {%4,%5,%6,%7}, {%8,%9}, {%0,%1,%2,%3};"
                        : "+f"(acc[tm][tn][0]), "+f"(acc[tm][tn][1]),
                          "+f"(acc[tm][tn][2]), "+f"(acc[tm][tn][3])
                        : "r"(af[tm][0]), "r"(af[tm][1]), "r"(af[tm][2]), "r"(af[tm][3]),
                          "r"(bf[tn][0]), "r"(bf[tn][1]));
                }
        }
    }

    #pragma unroll
    for (int tm = 0; tm < 2; tm++) {
        int row0 = m0 + wm + tm * 16 + g;
        #pragma unroll
        for (int tn = 0; tn < 8; tn++) {
            int col = n0 + wn + tn * 8 + tig * 2;
            float b0 = bias[col], b1 = bias[col + 1];
            float2 v0 = make_float2(acc[tm][tn][0] + b0, acc[tm][tn][1] + b1);
            float2 v1 = make_float2(acc[tm][tn][2] + b0, acc[tm][tn][3] + b1);
            *(float2*)(C + (size_t)row0 * N + col) = v0;
            *(float2*)(C + (size_t)(row0 + 8) * N + col) = v1;
        }
    }
}

// ============================================================================
// Bank-scheduled sparse compression of w_res (validated)
// ============================================================================
__global__ __launch_bounds__(256) void build_sparse_kernel(const float* __restrict__ wres)
{
    __shared__ unsigned long long bankused[8][32];
    __shared__ unsigned long long rmask[256];
    __shared__ int maxpos_s[8];
    __shared__ uint32_t padw_s[8][SPCAP];

    int r = blockIdx.x;
    int k = threadIdx.x;
    int w = k >> 5, lane = k & 31;

    if (lane == 0) maxpos_s[w] = -1;
    bankused[w][lane] = 0ull;
    rmask[k] = 0ull;

    int jlist[SPCAP]; float vlist[SPCAP];
    int cnt = 0;
    const float* rowp = wres + ((size_t)(r * SRES + k)) * SRES;
    for (int j = 0; j < SRES; j++) {
        float wv = rowp[j];
        if (wv != 0.0f && cnt < SPCAP) { jlist[cnt] = j; vlist[cnt] = wv; cnt++; }
    }
    __syncthreads();

    for (int l = 0; l < 32; l++) {
        if (lane == l) {
            unsigned long long rm = 0ull;
            int mp = maxpos_s[w];
            for (int i = 0; i < cnt; i++) {
                int bank = jlist[i] & 31;
                unsigned long long blocked = bankused[w][bank] | rm;
                unsigned long long freeM = ~blocked;
                int pos;
                if (freeM != 0ull) pos = __ffsll((long long)freeM) - 1;
                else {
                    unsigned long long f2m = ~rm;
                    if (f2m == 0ull) continue;
                    pos = __ffsll((long long)f2m) - 1;
                }
                if (pos < 0 || pos >= SPCAP) continue;
                bankused[w][bank] |= 1ull << pos;
                rm |= 1ull << pos;
                g_spv[r][pos][k] = vlist[i];
                g_spo[r][pos][k] = (uint32_t)(jlist[i] * 4);
                if (pos > mp) mp = pos;
            }
            rmask[k] = rm;
            maxpos_s[w] = mp;
        }
        __syncwarp();
    }
    __syncthreads();

    int np = ((maxpos_s[w] + 1) + 7) & ~7;
    if (np < 8) np = 8;
    if (np > SPCAP) np = SPCAP;

    for (int p = lane; p < SPCAP; p += 32) {
        uint32_t usedbanks = 0;
        #pragma unroll
        for (int bk = 0; bk < 32; bk++)
            usedbanks |= (uint32_t)((bankused[w][bk] >> p) & 1ull) << bk;
        uint32_t freeb = ~usedbanks;
        padw_s[w][p] = freeb ? (uint32_t)(__ffs(freeb) - 1) : 0u;
    }
    __syncthreads();

    unsigned long long rm = rmask[k];
    for (int p = 0; p < SPCAP; p++) {
        if (!((rm >> p) & 1ull)) {
            g_spv[r][p][k] = 0.0f;
            g_spo[r][p][k] = padw_s[w][p] * 4u;
        }
    }
    if (lane == 0) g_spn[r][w] = np;
}

// ============================================================================
// Flag reset (graph-replay determinism)
// ============================================================================
__global__ void zero_flags_kernel() {
    int i = threadIdx.x;
    if (i < BB * 16) { g_f1[i] = 0; g_f2[i] = 0; }
    if (i == 0) g_tilectr = 0;
}

// ============================================================================
// Scan block body (v3, validated) + f1 gating + f2 publishing
// ============================================================================
__device__ __forceinline__ float fast_tanh(float x) {
    return 1.0f - 2.0f / (__expf(2.0f * x) + 1.0f);
}

#define LDS_B0(dst, a) asm volatile("ld.shared.f32 %0, [%1];"      : "=f"(dst) : "r"(a))
#define LDS_B1(dst, a) asm volatile("ld.shared.f32 %0, [%1+1024];" : "=f"(dst) : "r"(a))

#define GATHER(LDSOP)                                                          \
    {                                                                          \
        a0 = 0.f; a1 = 0.f; a2 = 0.f; a3 = 0.f;                                \
        _Pragma("unroll")                                                      \
        for (int i = 0; i < SPCAP; i += 8) {                                   \
            if (i >= nslots) break;  /* warp-uniform */                        \
            float t0, t1, t2, t3, t4, t5, t6, t7;                              \
            LDSOP(t0, adr[i    ]); LDSOP(t1, adr[i + 1]);                      \
            LDSOP(t2, adr[i + 2]); LDSOP(t3, adr[i + 3]);                      \
            LDSOP(t4, adr[i + 4]); LDSOP(t5, adr[i + 5]);                      \
            LDSOP(t6, adr[i + 6]); LDSOP(t7, adr[i + 7]);                      \
            a0 = fmaf(val[i    ], t0, a0); a1 = fmaf(val[i + 1], t1, a1);      \
            a2 = fmaf(val[i + 2], t2, a2); a3 = fmaf(val[i + 3], t3, a3);      \
            a0 = fmaf(val[i + 4], t4, a0); a1 = fmaf(val[i + 5], t5, a1);      \
            a2 = fmaf(val[i + 6], t6, a2); a3 = fmaf(val[i + 7], t7, a3);      \
        }                                                                      \
    }

__device__ void scan_block(const float* __restrict__ prev, float* smembase)
{
    float* s  = smembase;              // [2][256]; buffer 1 at +1024 bytes
    float* sx = smembase + 2 * SRES;   // [2][XROWS][256]

    int chain = blockIdx.x;          // 0..15
    int b = chain >> 2, r = chain & 3;
    int k = threadIdx.x;             // row 0..255
    uint32_t sbase  = (uint32_t)__cvta_generic_to_shared(s);
    uint32_t sxbase = (uint32_t)__cvta_generic_to_shared(sx);

    const int nslots = g_spn[r][k >> 5];

    float    val[SPCAP];
    uint32_t adr[SPCAP];
    #pragma unroll
    for (int i = 0; i < SPCAP; i++) {
        val[i] = g_spv[r][i][k];
        adr[i] = g_spo[r][i][k] + sbase;
    }

    const float* xb0 = g_x + (size_t)b * TT * DRES + r * SRES;
    int xrow = k >> 6;
    int xoff = (k & 63) << 2;

    // gate tblk 0 x (gemm1 tiles for (b, tblk0) must be done: count 8)
    if (k == 0) {
        while (*(volatile int*)&g_f1[b * 16] < 8) { }
        __threadfence();
    }
    __syncthreads();

    // prologue: issue batches 0 and 1 (t < 16, all in tblk 0)
    #pragma unroll
    for (int bb = 0; bb < 2; bb++) {
        #pragma unroll
        for (int rnd = 0; rnd < 2; rnd++) {
            int j = xrow + rnd * 4;
            const float* src = xb0 + (size_t)(bb * XROWS + j) * DRES + xoff;
            uint32_t dst = sxbase + (uint32_t)((bb * XROWS * SRES + j * SRES + xoff) * 4);
            CP_ASYNC_CA16(dst, src);
        }
        CP_COMMIT();
    }

    float sreg = prev[b * DRES + r * SRES + k];
    s[k] = sreg;

    float* sp = g_states + (size_t)b * TT * DRES + r * SRES + k;
    __syncthreads();

    float a0, a1, a2, a3;
    for (int tb = 0; tb < NBLK; tb++) {
        CP_WAIT1();
        __syncthreads();
        int slot = tb & 1;

        #pragma unroll
        for (int u = 0; u < XROWS; u += 2) {
            float xv0 = sx[slot * XROWS * SRES + u * SRES + k];
            GATHER(LDS_B0);
            {
                float pre  = (a0 + a1) + (a2 + a3) + xv0;
                float snew = (1.0f - LEAK) * sreg + LEAK * fast_tanh(pre);
                sp[(size_t)(tb * XROWS + u) * DRES] = snew;
                s[SRES + k] = snew;
                sreg = snew;
            }
            __syncthreads();

            float xv1 = sx[slot * XROWS * SRES + (u + 1) * SRES + k];
            GATHER(LDS_B1);
            {
                float pre  = (a0 + a1) + (a2 + a3) + xv1;
                float snew = (1.0f - LEAK) * sreg + LEAK * fast_tanh(pre);
                sp[(size_t)(tb * XROWS + u + 1) * DRES] = snew;
                s[k] = snew;
                sreg = snew;
            }
            __syncthreads();
        }

        // publish f2 when a 128-step tblk completes (states visible to gemm2)
        if (((tb + 1) & 15) == 0) {
            __threadfence();
            __syncthreads();
            if (k == 0) atomicAdd(&g_f2[b * 16 + ((tb + 1) >> 4) - 1], 1);
        }

        // issue batch tb+2; gate on f1 at tblk boundaries
        int bb = tb + 2;
        if (bb < NBLK) {
            if ((bb & 15) == 0) {
                if (k == 0) {
                    while (*(volatile int*)&g_f1[b * 16 + (bb >> 4)] < 8) { }
                    __threadfence();
                }
                __syncthreads();
            }
            #pragma unroll
            for (int rnd = 0; rnd < 2; rnd++) {
                int j = xrow + rnd * 4;
                const float* src = xb0 + (size_t)(bb * XROWS + j) * DRES + xoff;
                uint32_t dst = sxbase + (uint32_t)((slot * XROWS * SRES + j * SRES + xoff) * 4);
                CP_ASYNC_CA16(dst, src);
            }
        }
        CP_COMMIT();
    }

    g_final[b * DRES + r * SRES + k] = sreg;
}

// ============================================================================
// Mega kernel: blocks 0..15 scan, 16..147 gemm workers (all resident)
// ============================================================================
__global__ __launch_bounds__(256) void mega_kernel(
    const float* __restrict__ hs,   const float* __restrict__ win,
    const float* __restrict__ bin,  const float* __restrict__ wout,
    const float* __restrict__ bout, const float* __restrict__ prev)
{
    extern __shared__ float smem[];
    int tid = threadIdx.x;

    if (blockIdx.x < NSCAN) {
        scan_block(prev, smem);
        return;
    }

    // ---- worker: pull tiles off the queue ----
    __shared__ int s_idx;
    for (;;) {
        if (tid == 0) s_idx = atomicAdd(&g_tilectr, 1);
        __syncthreads();
        int idx = s_idx;
        __syncthreads();
        if (idx >= NTILES) break;

        if (idx < NT1) {
            // gemm1 tile: x = hs @ w_in + b_in ; order: tblk-major
            int tblk = idx >> 5;            // /32
            int rem  = idx & 31;
            int b    = rem >> 3;
            int n    = rem & 7;
            int m0   = (b * 16 + tblk) * 128;
            gemm_tile(hs, win, bin, g_x, DRES, HID, m0, n * 128, smem);
            __threadfence();
            __syncthreads();
            if (tid == 0) atomicAdd(&g_f1[b * 16 + tblk], 1);
        } else {
            // gemm2 tile: out = states @ w_out + b_out ; gated on scan progress
            int j    = idx - NT1;
            int tblk = j >> 6;              // /64
            int rem  = j & 63;
            int b    = rem >> 4;
            int n    = rem & 15;
            int m0   = (b * 16 + tblk) * 128;
            if (tid == 0) {
                while (*(volatile int*)&g_f2[b * 16 + tblk] < 4) { }
                __threadfence();
            }
            __syncthreads();
            gemm_tile(g_states, wout, bout, g_out, HID, DRES, m0, n * 128, smem);
        }
        __syncthreads();
    }
}

// ============================================================================
// RMSNorm epilogue
// ============================================================================
__global__ __launch_bounds__(256) void rmsnorm_kernel(
    const float* __restrict__ hs, const float* __restrict__ ot,
    const float* __restrict__ lnw, float* __restrict__ y)
{
    __shared__ float red[8];
    int row = blockIdx.x, tid = threadIdx.x;
    const float4* h4 = (const float4*)(hs + (size_t)row * HID);
    const float4* o4 = (const float4*)(ot + (size_t)row * HID);
    const float4* l4 = (const float4*)lnw;
    float4* y4 = (float4*)(y + (size_t)row * HID);

    float4 v[2];
    float ss = 0.f;
    #pragma unroll
    for (int i = 0; i < 2; i++) {
        int idx = tid + i * 256;
        float4 a = h4[idx], b = o4[idx];
        float4 s = make_float4(a.x + b.x, a.y + b.y, a.z + b.z, a.w + b.w);
        v[i] = s;
        ss += s.x * s.x + s.y * s.y + s.z * s.z + s.w * s.w;
    }
    #pragma unroll
    for (int off = 16; off; off >>= 1) ss += __shfl_xor_sync(0xffffffffu, ss, off);
    if ((tid & 31) == 0) red[tid >> 5] = ss;
    __syncthreads();
    float tot = 0.f;
    #pragma unroll
    for (int i = 0; i < 8; i++) tot += red[i];
    float scale = rsqrtf(tot * (1.0f / HID) + 1e-6f);
    #pragma unroll
    for (int i = 0; i < 2; i++) {
        int idx = tid + i * 256;
        float4 lw = l4[idx];
        float4 s = v[i];
        y4[idx] = make_float4(s.x * scale * lw.x, s.y * scale * lw.y,
                              s.z * scale * lw.z, s.w * scale * lw.w);
    }
}

__global__ void copy_final_kernel(float* __restrict__ dst) {
    int i = blockIdx.x * 256 + threadIdx.x;
    if (i < BB * DRES) dst[i] = g_final[i];
}

// ============================================================================
extern "C" void kernel_launch(void* const* d_in, const int* in_sizes, int n_in,
                              void* d_out, int out_size)
{
    const float* hs   = (const float*)d_in[0];
    const float* prev = (const float*)d_in[1];
    const float* w_in = (const float*)d_in[2];
    const float* b_in = (const float*)d_in[3];
    const float* wres = (const float*)d_in[4];
    const float* wout = (const float*)d_in[5];
    const float* bout = (const float*)d_in[6];
    const float* lnw  = (const float*)d_in[7];
    float* out = (float*)d_out;

    void* po;
    cudaGetSymbolAddress(&po, g_out);
    float* go = (float*)po;

    static bool attr_set = false;
    if (!attr_set) {
        cudaFuncSetAttribute(mega_kernel,
                             cudaFuncAttributeMaxDynamicSharedMemorySize,
                             GEMM_SMEM_BYTES);
        attr_set = true;
    }

    // 0) reset flags (determinism across graph replays)
    zero_flags_kernel<<<1, 128>>>();

    // 1) bank-scheduled sparse compression
    build_sparse_kernel<<<NRES, 256>>>(wres);

    // 2) fused gemm1 + scan + gemm2, streaming-overlapped
    mega_kernel<<<NGRID, 256, GEMM_SMEM_BYTES>>>(hs, w_in, b_in, wout, bout, prev);

    // 3) y = RMSNorm(hs + out) * ln_w
    rmsnorm_kernel<<<MROWS, 256>>>(hs, go, lnw, out);

    // 4) final state appended after y (if the output buffer carries it)
    if (out_size >= MROWS * HID + BB * DRES) {
        float* fdst = out + (out_size - BB * DRES);
        copy_final_kernel<<<(BB * DRES + 255) / 256, 256>>>(fdst);
    }
}